// round 5
// baseline (speedup 1.0000x reference)
#include <cuda_runtime.h>
#include <cuda_bf16.h>
#include <cstdint>

typedef __nv_bfloat16 bf16;

// Output layout (floats): out, z_all, key_rope_all, attn_weights, scores
#define OUT_OUT    0L
#define OUT_ZALL   4194304L
#define OUT_KRA    8388608L
#define OUT_ATTN   12582912L
#define OUT_SCORES 79691776L

// ---------------------------------------------------------------------------
// Scratch
// ---------------------------------------------------------------------------
__device__ float g_query [2048L*1024];
__device__ float g_qx    [2048L*1024];
__device__ float g_qrope [2048L*1024];
__device__ float g_kx    [2048L*1024];
__device__ float g_keyc  [4096L*1024];
__device__ float g_value [4096L*1024];

__device__ bf16 g_xh[2048L*2048], g_xl[2048L*2048];
__device__ bf16 g_zallh[4096L*1024], g_zalll[4096L*1024];
__device__ bf16 g_qlath[2048L*1024], g_qlatl[2048L*1024];
__device__ bf16 g_qfh[4194304L], g_qfl[4194304L];
__device__ bf16 g_kfh[8388608L], g_kfl[8388608L];
__device__ bf16 g_vth[2L*1024*2048], g_vtl[2L*1024*2048];
__device__ bf16 g_hoh[2048L*1024], g_hol[2048L*1024];

__device__ bf16 g_WlatTh[2097152], g_WlatTl[2097152];
__device__ bf16 g_WqdTh [2097152], g_WqdTl [2097152];
__device__ bf16 g_WquTh [1048576], g_WquTl [1048576];
__device__ bf16 g_WxrTh [1048576], g_WxrTl [1048576];
__device__ bf16 g_WkuTh [1048576], g_WkuTl [1048576];
__device__ bf16 g_WvuTh [1048576], g_WvuTl [1048576];
__device__ bf16 g_WkrTh [2097152], g_WkrTl [2097152];
__device__ bf16 g_WoTh  [2097152], g_WoTl  [2097152];

// ---------------------------------------------------------------------------
// Helpers (baseline PTX only)
// ---------------------------------------------------------------------------
__device__ __forceinline__ uint32_t smem_u32(const void* p) {
    uint32_t a;
    asm("{ .reg .u64 t; cvta.to.shared.u64 t, %1; cvt.u32.u64 %0, t; }" : "=r"(a) : "l"(p));
    return a;
}
#define SW128X(o) ((o) ^ (((o) >> 3) & 0x70))

__device__ __forceinline__ void ldm4(uint32_t* r, uint32_t addr) {
    asm volatile("ldmatrix.sync.aligned.m8n8.x4.shared.b16 {%0,%1,%2,%3}, [%4];"
        : "=r"(r[0]), "=r"(r[1]), "=r"(r[2]), "=r"(r[3]) : "r"(addr));
}
__device__ __forceinline__ void mma_bf16(float* c, const uint32_t* a, const uint32_t* b) {
    asm volatile("mma.sync.aligned.m16n8k16.row.col.f32.bf16.bf16.f32 "
        "{%0,%1,%2,%3}, {%4,%5,%6,%7}, {%8,%9}, {%0,%1,%2,%3};"
        : "+f"(c[0]), "+f"(c[1]), "+f"(c[2]), "+f"(c[3])
        : "r"(a[0]), "r"(a[1]), "r"(a[2]), "r"(a[3]), "r"(b[0]), "r"(b[1]));
}

// ---------------------------------------------------------------------------
// Split-bf16 HMMA GEMM (unchanged from round 4, NT=128 only)
// ---------------------------------------------------------------------------
template<int NT>
__global__ void __launch_bounds__(256) gemm_tc(
    const bf16* __restrict__ Ah, const bf16* __restrict__ Al,
    const bf16* __restrict__ Bh, const bf16* __restrict__ Bl,
    float* C, const float* bias, bf16* Ch, bf16* Cl,
    int K, int lda, int ldb, int ldc,
    int HD, long sA1, long sA2, long sB1, long sB2, long sC1, long sC2,
    float alpha)
{
    constexpr int MI  = (NT == 128) ? 4 : 2;
    constexpr int NB  = NT / 32;
    constexpr int ABY = 128 * 128;
    constexpr int BBY = NT * 128;

    extern __shared__ char smem[];
    uint32_t base = (smem_u32(smem) + 1023u) & ~1023u;
    uint32_t aT[2] = {base, base + ABY};
    uint32_t bT[2] = {base + 2u*ABY, base + 2u*ABY + (uint32_t)BBY};

    int tid = threadIdx.x;
    int lane = tid & 31, wid = tid >> 5;

    int wm = (NT == 128) ? (wid & 1) * 64 : (wid & 3) * 32;
    int wn = (NT == 128) ? (wid >> 1) * 32 : (wid >> 2) * 32;

    int z = blockIdx.z;
    int z1 = z / HD, z2 = z - z1 * HD;
    long aoff = (long)z1*sA1 + (long)z2*sA2 + (long)blockIdx.y*128*lda;
    long boff = (long)z1*sB1 + (long)z2*sB2 + (long)blockIdx.x*NT*ldb;
    const bf16 *Abh = Ah + aoff, *Abl = Al + aoff;
    const bf16 *Bbh = Bh + boff, *Bbl = Bl + boff;

    int a_r = (lane & 7) + (((lane >> 3) & 1) << 3);
    int a_c = (lane >> 4) & 1;
    int b_r = (lane & 7) + ((lane & 16) ? 8 : 0);
    int b_c = (lane >> 3) & 1;

    float acc[MI][4][4];
    #pragma unroll
    for (int i = 0; i < MI; i++)
        #pragma unroll
        for (int j = 0; j < 4; j++)
            #pragma unroll
            for (int q = 0; q < 4; q++) acc[i][j][q] = 0.f;

    int kc = K >> 6;
    int nch = 3 * kc;
    int lr = tid >> 3, lc = tid & 7;

    {
        #pragma unroll
        for (int it = 0; it < 4; it++) {
            int r = lr + it * 32;
            uint4 v = *(const uint4*)(Abh + (long)r * lda + lc * 8);
            asm volatile("st.shared.v4.b32 [%0], {%1,%2,%3,%4};"
                :: "r"(aT[0] + SW128X(r*128 + lc*16)), "r"(v.x), "r"(v.y), "r"(v.z), "r"(v.w));
        }
        #pragma unroll
        for (int it = 0; it < NB; it++) {
            int r = lr + it * 32;
            uint4 v = *(const uint4*)(Bbh + (long)r * ldb + lc * 8);
            asm volatile("st.shared.v4.b32 [%0], {%1,%2,%3,%4};"
                :: "r"(bT[0] + SW128X(r*128 + lc*16)), "r"(v.x), "r"(v.y), "r"(v.z), "r"(v.w));
        }
    }
    __syncthreads();

    uint4 pa[4], pb[NB];
    for (int c = 0; c < nch; c++) {
        int cur = c & 1;
        bool more = (c + 1 < nch);
        if (more) {
            int cn = c + 1;
            int pass = cn / kc;
            int kk = (cn - pass * kc) << 6;
            const bf16* Ap = (pass == 1) ? Abl : Abh;
            const bf16* Bp = (pass == 2) ? Bbl : Bbh;
            #pragma unroll
            for (int it = 0; it < 4; it++)
                pa[it] = *(const uint4*)(Ap + (long)(lr + it*32) * lda + kk + lc * 8);
            #pragma unroll
            for (int it = 0; it < NB; it++)
                pb[it] = *(const uint4*)(Bp + (long)(lr + it*32) * ldb + kk + lc * 8);
        }

        uint32_t at = aT[cur], bt = bT[cur];
        #pragma unroll
        for (int ks = 0; ks < 4; ks++) {
            uint32_t af[MI][4], bfr[8];
            #pragma unroll
            for (int mi = 0; mi < MI; mi++) {
                int row = wm + mi*16 + a_r;
                ldm4(af[mi], at + row*128 + ((((ks<<1) + a_c) ^ (row & 7)) << 4));
            }
            #pragma unroll
            for (int np = 0; np < 2; np++) {
                int row = wn + np*16 + b_r;
                ldm4(&bfr[np*4], bt + row*128 + ((((ks<<1) + b_c) ^ (row & 7)) << 4));
            }
            #pragma unroll
            for (int mi = 0; mi < MI; mi++)
                #pragma unroll
                for (int ni = 0; ni < 4; ni++)
                    mma_bf16(acc[mi][ni], af[mi], &bfr[ni*2]);
        }

        if (more) {
            int nxt = cur ^ 1;
            #pragma unroll
            for (int it = 0; it < 4; it++) {
                int r = lr + it * 32;
                asm volatile("st.shared.v4.b32 [%0], {%1,%2,%3,%4};"
                    :: "r"(aT[nxt] + SW128X(r*128 + lc*16)),
                       "r"(pa[it].x), "r"(pa[it].y), "r"(pa[it].z), "r"(pa[it].w));
            }
            #pragma unroll
            for (int it = 0; it < NB; it++) {
                int r = lr + it * 32;
                asm volatile("st.shared.v4.b32 [%0], {%1,%2,%3,%4};"
                    :: "r"(bT[nxt] + SW128X(r*128 + lc*16)),
                       "r"(pb[it].x), "r"(pb[it].y), "r"(pb[it].z), "r"(pb[it].w));
            }
        }
        __syncthreads();
    }

    long coff = (long)z1*sC1 + (long)z2*sC2
              + (long)blockIdx.y*128*ldc + (long)blockIdx.x*NT;
    int colg0 = blockIdx.x * NT;
    #pragma unroll
    for (int mi = 0; mi < MI; mi++) {
        #pragma unroll
        for (int ni = 0; ni < 4; ni++) {
            int col = wn + ni*8 + (lane & 3)*2;
            float bv0 = 0.f, bv1 = 0.f;
            if (bias) { bv0 = bias[colg0 + col]; bv1 = bias[colg0 + col + 1]; }
            int r0 = wm + mi*16 + (lane >> 2);
            float v00 = acc[mi][ni][0]*alpha + bv0, v01 = acc[mi][ni][1]*alpha + bv1;
            float v10 = acc[mi][ni][2]*alpha + bv0, v11 = acc[mi][ni][3]*alpha + bv1;
            if (C) {
                *(float2*)(C + coff + (long)r0*ldc + col)       = make_float2(v00, v01);
                *(float2*)(C + coff + (long)(r0+8)*ldc + col)   = make_float2(v10, v11);
            }
            if (Ch) {
                bf16 h00 = __float2bfloat16(v00), h01 = __float2bfloat16(v01);
                bf16 h10 = __float2bfloat16(v10), h11 = __float2bfloat16(v11);
                *(__nv_bfloat162*)(Ch + coff + (long)r0*ldc + col) = __nv_bfloat162(h00, h01);
                *(__nv_bfloat162*)(Ch + coff + (long)(r0+8)*ldc + col) = __nv_bfloat162(h10, h11);
                bf16 l00 = __float2bfloat16(v00 - __bfloat162float(h00));
                bf16 l01 = __float2bfloat16(v01 - __bfloat162float(h01));
                bf16 l10 = __float2bfloat16(v10 - __bfloat162float(h10));
                bf16 l11 = __float2bfloat16(v11 - __bfloat162float(h11));
                *(__nv_bfloat162*)(Cl + coff + (long)r0*ldc + col) = __nv_bfloat162(l00, l01);
                *(__nv_bfloat162*)(Cl + coff + (long)(r0+8)*ldc + col) = __nv_bfloat162(l10, l11);
            }
        }
    }
}

// ---------------------------------------------------------------------------
// Fused softmax + probs@V.
// grid (8 mtiles, 32 z=(b*16+h)), 256 threads.
// Reads scores strip once, writes attn (unmasked softmax), computes masked
// probs in SMEM (bf16 hi/lo) and runs 3-term HMMA against V (vth/vtl).
// ---------------------------------------------------------------------------
__global__ void __launch_bounds__(256) fused_sm_av(
    const float* __restrict__ scores, const int* __restrict__ vlens,
    float* __restrict__ attn,
    const bf16* __restrict__ Vh, const bf16* __restrict__ Vl,
    bf16* __restrict__ Oh, bf16* __restrict__ Ol)
{
    extern __shared__ char smem[];
    char* ali = (char*)(((uintptr_t)smem + 1023u) & ~(uintptr_t)1023u);
    uint32_t base = smem_u32(ali);
    const uint32_t PH = base, PL = base + 16384u, VH = base + 32768u, VL = base + 40960u;
    float4* s_stats = (float4*)(ali + 49152);   // per-row: mu, iu, mm, im
    int*    s_vl    = (int*)(ali + 51200);

    int tid = threadIdx.x;
    int lane = tid & 31, wid = tid >> 5;
    int z = blockIdx.y;             // b*16 + h
    int b = z >> 4, h = z & 15;
    int mtile = blockIdx.x;

    const float* strip = scores + (long)z * (1024L*2048) + (long)mtile * 128 * 2048;
    float*       astrip = attn  + (long)z * (1024L*2048) + (long)mtile * 128 * 2048;
    const bf16*  Vhp = Vh + (long)b * (1024L*2048) + (long)h * 64 * 2048;
    const bf16*  Vlp = Vl + (long)b * (1024L*2048) + (long)h * 64 * 2048;

    if (tid < 128) s_vl[tid] = vlens[b * 1024 + mtile * 128 + tid];
    __syncthreads();

    // ---- Phase 1: per-row stats (warp per 16 rows) ----
    for (int rr = 0; rr < 16; rr++) {
        int r = wid * 16 + rr;
        const float4* row = (const float4*)(strip + (long)r * 2048);
        int vl = s_vl[r];
        float um = -1e30f, mm = -1e30f;
        #pragma unroll 4
        for (int j = 0; j < 16; j++) {
            float4 v = row[lane + j * 32];
            int c0 = (lane + j * 32) << 2;
            um = fmaxf(um, fmaxf(fmaxf(v.x, v.y), fmaxf(v.z, v.w)));
            if (c0 + 0 < vl) mm = fmaxf(mm, v.x);
            if (c0 + 1 < vl) mm = fmaxf(mm, v.y);
            if (c0 + 2 < vl) mm = fmaxf(mm, v.z);
            if (c0 + 3 < vl) mm = fmaxf(mm, v.w);
        }
        #pragma unroll
        for (int o = 16; o > 0; o >>= 1) {
            um = fmaxf(um, __shfl_xor_sync(0xffffffffu, um, o));
            mm = fmaxf(mm, __shfl_xor_sync(0xffffffffu, mm, o));
        }
        float us = 0.f, ms = 0.f;
        #pragma unroll 4
        for (int j = 0; j < 16; j++) {
            float4 v = row[lane + j * 32];
            int c0 = (lane + j * 32) << 2;
            us += expf(v.x - um) + expf(v.y - um) + expf(v.z - um) + expf(v.w - um);
            ms += ((c0 + 0 < vl) ? expf(v.x - mm) : 0.f)
                + ((c0 + 1 < vl) ? expf(v.y - mm) : 0.f)
                + ((c0 + 2 < vl) ? expf(v.z - mm) : 0.f)
                + ((c0 + 3 < vl) ? expf(v.w - mm) : 0.f);
        }
        #pragma unroll
        for (int o = 16; o > 0; o >>= 1) {
            us += __shfl_xor_sync(0xffffffffu, us, o);
            ms += __shfl_xor_sync(0xffffffffu, ms, o);
        }
        if (lane == 0) s_stats[r] = make_float4(um, 1.f / us, mm, 1.f / ms);
    }
    __syncthreads();

    // ---- Phase 2: chunked attn write + probs + HMMA AV ----
    int colq = tid & 15, rowg = tid >> 4;   // P loader: col quad, row group (8 rows)
    int a_r = (lane & 7) + (((lane >> 3) & 1) << 3);
    int a_c = (lane >> 4) & 1;
    int b_r = (lane & 7) + ((lane & 16) ? 8 : 0);
    int b_c = (lane >> 3) & 1;

    float acc[8][4];
    #pragma unroll
    for (int i = 0; i < 8; i++)
        #pragma unroll
        for (int q = 0; q < 4; q++) acc[i][q] = 0.f;

    for (int ch = 0; ch < 32; ch++) {
        int k0 = ch << 6;
        // P tiles: 128 rows x 64 cols
        #pragma unroll
        for (int i = 0; i < 8; i++) {
            int r = rowg * 8 + i;
            float4 v = *(const float4*)(strip + (long)r * 2048 + k0 + colq * 4);
            float4 st = s_stats[r];
            float4 eu;
            eu.x = expf(v.x - st.x) * st.y;
            eu.y = expf(v.y - st.x) * st.y;
            eu.z = expf(v.z - st.x) * st.y;
            eu.w = expf(v.w - st.x) * st.y;
            *(float4*)(astrip + (long)r * 2048 + k0 + colq * 4) = eu;
            int vl = s_vl[r];
            int c = k0 + colq * 4;
            float p0 = (c + 0 < vl) ? expf(v.x - st.z) * st.w : 0.f;
            float p1 = (c + 1 < vl) ? expf(v.y - st.z) * st.w : 0.f;
            float p2 = (c + 2 < vl) ? expf(v.z - st.z) * st.w : 0.f;
            float p3 = (c + 3 < vl) ? expf(v.w - st.z) * st.w : 0.f;
            bf16 h0 = __float2bfloat16(p0), h1 = __float2bfloat16(p1);
            bf16 h2 = __float2bfloat16(p2), h3 = __float2bfloat16(p3);
            bf16 l0 = __float2bfloat16(p0 - __bfloat162float(h0));
            bf16 l1 = __float2bfloat16(p1 - __bfloat162float(h1));
            bf16 l2 = __float2bfloat16(p2 - __bfloat162float(h2));
            bf16 l3 = __float2bfloat16(p3 - __bfloat162float(h3));
            uint32_t off = SW128X((uint32_t)(r * 128 + colq * 8));
            uint32_t hu0 = ((__nv_bfloat16_raw)h0).x | ((uint32_t)((__nv_bfloat16_raw)h1).x << 16);
            uint32_t hu1 = ((__nv_bfloat16_raw)h2).x | ((uint32_t)((__nv_bfloat16_raw)h3).x << 16);
            uint32_t lu0 = ((__nv_bfloat16_raw)l0).x | ((uint32_t)((__nv_bfloat16_raw)l1).x << 16);
            uint32_t lu1 = ((__nv_bfloat16_raw)l2).x | ((uint32_t)((__nv_bfloat16_raw)l3).x << 16);
            asm volatile("st.shared.v2.b32 [%0], {%1,%2};" :: "r"(PH + off), "r"(hu0), "r"(hu1));
            asm volatile("st.shared.v2.b32 [%0], {%1,%2};" :: "r"(PL + off), "r"(lu0), "r"(lu1));
        }
        // V tiles: 64 n-rows x 64 k-cols (hi + lo)
        #pragma unroll
        for (int it = 0; it < 2; it++) {
            int slot = tid + it * 256;
            int n = slot >> 3, c16 = slot & 7;
            uint4 vh = *(const uint4*)(Vhp + (long)n * 2048 + k0 + c16 * 8);
            uint4 vl4 = *(const uint4*)(Vlp + (long)n * 2048 + k0 + c16 * 8);
            uint32_t off = SW128X((uint32_t)(n * 128 + c16 * 16));
            asm volatile("st.shared.v4.b32 [%0], {%1,%2,%3,%4};"
                :: "r"(VH + off), "r"(vh.x), "r"(vh.y), "r"(vh.z), "r"(vh.w));
            asm volatile("st.shared.v4.b32 [%0], {%1,%2,%3,%4};"
                :: "r"(VL + off), "r"(vl4.x), "r"(vl4.y), "r"(vl4.z), "r"(vl4.w));
        }
        __syncthreads();

        #pragma unroll
        for (int ks = 0; ks < 4; ks++) {
            uint32_t aph[4], apl[4], bh[16], bl[16];
            int arow = wid * 16 + a_r;
            uint32_t aoffs = (uint32_t)((((ks << 1) + a_c) ^ (arow & 7)) << 4);
            ldm4(aph, PH + arow * 128 + aoffs);
            ldm4(apl, PL + arow * 128 + aoffs);
            #pragma unroll
            for (int np = 0; np < 4; np++) {
                int brow = np * 16 + b_r;
                uint32_t boff = (uint32_t)((((ks << 1) + b_c) ^ (brow & 7)) << 4);
                ldm4(&bh[np * 4], VH + brow * 128 + boff);
                ldm4(&bl[np * 4], VL + brow * 128 + boff);
            }
            #pragma unroll
            for (int ni = 0; ni < 8; ni++) {
                mma_bf16(acc[ni], aph, &bh[ni * 2]);
                mma_bf16(acc[ni], apl, &bh[ni * 2]);
                mma_bf16(acc[ni], aph, &bl[ni * 2]);
            }
        }
        __syncthreads();
    }

    // epilogue: head_out rows l = mtile*128 + row, cols h*64 + n
    long obase = (long)b * (1024L * 1024) + (long)(mtile * 128) * 1024 + h * 64;
    #pragma unroll
    for (int ni = 0; ni < 8; ni++) {
        int col = ni * 8 + (lane & 3) * 2;
        int r0 = wid * 16 + (lane >> 2);
        float v00 = acc[ni][0], v01 = acc[ni][1];
        float v10 = acc[ni][2], v11 = acc[ni][3];
        bf16 h00 = __float2bfloat16(v00), h01 = __float2bfloat16(v01);
        bf16 h10 = __float2bfloat16(v10), h11 = __float2bfloat16(v11);
        *(__nv_bfloat162*)(Oh + obase + (long)r0 * 1024 + col)     = __nv_bfloat162(h00, h01);
        *(__nv_bfloat162*)(Oh + obase + (long)(r0+8) * 1024 + col) = __nv_bfloat162(h10, h11);
        bf16 l00 = __float2bfloat16(v00 - __bfloat162float(h00));
        bf16 l01 = __float2bfloat16(v01 - __bfloat162float(h01));
        bf16 l10 = __float2bfloat16(v10 - __bfloat162float(h10));
        bf16 l11 = __float2bfloat16(v11 - __bfloat162float(h11));
        *(__nv_bfloat162*)(Ol + obase + (long)r0 * 1024 + col)     = __nv_bfloat162(l00, l01);
        *(__nv_bfloat162*)(Ol + obase + (long)(r0+8) * 1024 + col) = __nv_bfloat162(l10, l11);
    }
}

// ---------------------------------------------------------------------------
// Elementwise helpers
// ---------------------------------------------------------------------------
__global__ void split_kernel(const float* __restrict__ in, bf16* __restrict__ oh,
                             bf16* __restrict__ ol, long n)
{
    long i = ((long)blockIdx.x * 256 + threadIdx.x) * 4;
    if (i >= n) return;
    float4 v = *(const float4*)(in + i);
    float a[4] = {v.x, v.y, v.z, v.w};
    bf16 h[4], l[4];
    #pragma unroll
    for (int k = 0; k < 4; k++) {
        h[k] = __float2bfloat16(a[k]);
        l[k] = __float2bfloat16(a[k] - __bfloat162float(h[k]));
    }
    *(__nv_bfloat162*)(oh + i)     = __nv_bfloat162(h[0], h[1]);
    *(__nv_bfloat162*)(oh + i + 2) = __nv_bfloat162(h[2], h[3]);
    *(__nv_bfloat162*)(ol + i)     = __nv_bfloat162(l[0], l[1]);
    *(__nv_bfloat162*)(ol + i + 2) = __nv_bfloat162(l[2], l[3]);
}

__global__ void transpose_split(const float* __restrict__ in, bf16* __restrict__ oh,
                                bf16* __restrict__ ol, int R, int C, long sIn, long sOut)
{
    __shared__ float t[32][33];
    long ib = (long)blockIdx.z * sIn, ob = (long)blockIdx.z * sOut;
    int x = blockIdx.x * 32 + threadIdx.x;
    int y0 = blockIdx.y * 32;
    #pragma unroll
    for (int j = threadIdx.y; j < 32; j += 8)
        t[j][threadIdx.x] = in[ib + (long)(y0 + j) * C + x];
    __syncthreads();
    int ox = blockIdx.y * 32 + threadIdx.x;
    int oy0 = blockIdx.x * 32;
    #pragma unroll
    for (int j = threadIdx.y; j < 32; j += 8) {
        float v = t[threadIdx.x][j];
        bf16 h = __float2bfloat16(v);
        long o = ob + (long)(oy0 + j) * R + ox;
        oh[o] = h;
        ol[o] = __float2bfloat16(v - __bfloat162float(h));
    }
}

__global__ void copy_concat_kernel(const float* __restrict__ src, float* __restrict__ dst)
{
    long i = (long)blockIdx.x * 256 + threadIdx.x;
    if (i >= 2L * 1024 * 1024) return;
    long r = i >> 10, c = i & 1023;
    long b = r >> 10, l = r & 1023;
    dst[((b * 2048) + l) * 1024 + c] = src[i];
}

// copy + split (for z -> z_all rows 0..1023, emitting zh/zl too)
__global__ void copy_concat_split(const float* __restrict__ src, float* __restrict__ dst,
                                  bf16* __restrict__ oh, bf16* __restrict__ ol)
{
    long i = (long)blockIdx.x * 256 + threadIdx.x;
    if (i >= 2L * 1024 * 1024) return;
    long r = i >> 10, c = i & 1023;
    long b = r >> 10, l = r & 1023;
    long o = ((b * 2048) + l) * 1024 + c;
    float v = src[i];
    dst[o] = v;
    bf16 h = __float2bfloat16(v);
    oh[o] = h;
    ol[o] = __float2bfloat16(v - __bfloat162float(h));
}

__global__ void rotary_kernel(const float* __restrict__ src, float* __restrict__ dst, int mode)
{
    int idx = blockIdx.x * 256 + threadIdx.x;
    if (idx >= 2048 * 16 * 32) return;
    int i = idx & 31;
    int h = (idx >> 5) & 15;
    int r = idx >> 9;
    int pos = r & 1023;
    float fr = expf(-9.2103403719761836f * (float)i / 32.0f);
    float ang = (float)pos * fr;
    float sn, cs;
    sincosf(ang, &sn, &cs);
    const float* s = src + (long)r * 1024 + h * 64 + i;
    float s1 = s[0], s2 = s[32];
    long drow = mode ? ((long)(r >> 10) * 2048 + 1024 + (r & 1023)) : (long)r;
    float* d = dst + drow * 1024 + h * 64 + i;
    d[0]  = s1 * cs - s2 * sn;
    d[32] = s1 * sn + s2 * cs;
}

__global__ void pack_q_split(const float* __restrict__ q, const float* __restrict__ qr,
                             bf16* __restrict__ qh, bf16* __restrict__ ql)
{
    long idx = (long)blockIdx.x * 256 + threadIdx.x;
    if (idx >= 4194304L) return;
    long d = idx & 127, l = (idx >> 7) & 1023, h = (idx >> 17) & 15, b = idx >> 21;
    long c = h * 128 + d;
    const float* src = (c < 1024) ? q : qr;
    float v = src[(b * 1024 + l) * 1024 + (c & 1023)];
    bf16 hh = __float2bfloat16(v);
    qh[idx] = hh;
    ql[idx] = __float2bfloat16(v - __bfloat162float(hh));
}

__global__ void pack_k_split(const float* __restrict__ kc, const float* __restrict__ kra,
                             bf16* __restrict__ kh, bf16* __restrict__ kl)
{
    long idx = (long)blockIdx.x * 256 + threadIdx.x;
    if (idx >= 8388608L) return;
    long d = idx & 127, kv = (idx >> 7) & 2047, h = (idx >> 18) & 15, b = idx >> 22;
    long c = h * 128 + d;
    const float* src = (c < 1024) ? kc : kra;
    float v = src[(b * 2048 + kv) * 1024 + (c & 1023)];
    bf16 hh = __float2bfloat16(v);
    kh[idx] = hh;
    kl[idx] = __float2bfloat16(v - __bfloat162float(hh));
}

// ---------------------------------------------------------------------------
// Host launch
// ---------------------------------------------------------------------------
#define GSYM(p, s) cudaGetSymbolAddress((void**)&(p), s)

extern "C" void kernel_launch(void* const* d_in, const int* in_sizes, int n_in,
                              void* d_out, int out_size)
{
    const float* x        = (const float*)d_in[0];
    const float* z        = (const float*)d_in[1];
    const float* key_rope = (const float*)d_in[2];
    const int*   vlens    = (const int*)  d_in[3];
    const float* W_latent = (const float*)d_in[4];
    const float* W_q_down = (const float*)d_in[5];
    const float* b_q_down = (const float*)d_in[6];
    const float* W_q_up   = (const float*)d_in[7];
    const float* W_k_up   = (const float*)d_in[8];
    const float* W_v_up   = (const float*)d_in[9];
    const float* W_x_rope = (const float*)d_in[10];
    const float* W_k_rope = (const float*)d_in[11];
    const float* W_o      = (const float*)d_in[12];
    float* out = (float*)d_out;

    float *p_query, *p_qx, *p_qrope, *p_kx, *p_keyc, *p_value;
    bf16 *xh, *xl, *zh, *zl, *qlh, *qll, *qfh, *qfl, *kfh, *kfl,
         *vth, *vtl, *hoh, *hol;
    bf16 *WlatTh, *WlatTl, *WqdTh, *WqdTl, *WquTh, *WquTl, *WxrTh, *WxrTl,
         *WkuTh, *WkuTl, *WvuTh, *WvuTl, *WkrTh, *WkrTl, *WoTh, *WoTl;

    GSYM(p_query, g_query); GSYM(p_qx, g_qx); GSYM(p_qrope, g_qrope);
    GSYM(p_kx, g_kx); GSYM(p_keyc, g_keyc); GSYM(p_value, g_value);
    GSYM(xh, g_xh); GSYM(xl, g_xl); GSYM(zh, g_zallh); GSYM(zl, g_zalll);
    GSYM(qlh, g_qlath); GSYM(qll, g_qlatl);
    GSYM(qfh, g_qfh); GSYM(qfl, g_qfl); GSYM(kfh, g_kfh); GSYM(kfl, g_kfl);
    GSYM(vth, g_vth); GSYM(vtl, g_vtl); GSYM(hoh, g_hoh); GSYM(hol, g_hol);
    GSYM(WlatTh, g_WlatTh); GSYM(WlatTl, g_WlatTl);
    GSYM(WqdTh, g_WqdTh);   GSYM(WqdTl, g_WqdTl);
    GSYM(WquTh, g_WquTh);   GSYM(WquTl, g_WquTl);
    GSYM(WxrTh, g_WxrTh);   GSYM(WxrTl, g_WxrTl);
    GSYM(WkuTh, g_WkuTh);   GSYM(WkuTl, g_WkuTl);
    GSYM(WvuTh, g_WvuTh);   GSYM(WvuTl, g_WvuTl);
    GSYM(WkrTh, g_WkrTh);   GSYM(WkrTl, g_WkrTl);
    GSYM(WoTh, g_WoTh);     GSYM(WoTl, g_WoTl);

    const int SM128 = 66560;
    const int SMF   = 53760;
    cudaFuncSetAttribute(gemm_tc<128>, cudaFuncAttributeMaxDynamicSharedMemorySize, SM128);
    cudaFuncSetAttribute(fused_sm_av,  cudaFuncAttributeMaxDynamicSharedMemorySize, SMF);
    dim3 tb(32, 8);

    // --- launches ordered so #6 is the x@W_latent GEMM (ncu -s 5 -c 1 target) ---
    split_kernel<<<4096, 256>>>(x, xh, xl, 4194304L);                             // 1
    transpose_split<<<dim3(32, 64, 1), tb>>>(W_latent, WlatTh, WlatTl, 2048, 1024, 0, 0); // 2
    copy_concat_split<<<8192, 256>>>(z, out + OUT_ZALL, zh, zl);                  // 3
    copy_concat_kernel<<<8192, 256>>>(key_rope, out + OUT_KRA);                   // 4
    transpose_split<<<dim3(32, 64, 1), tb>>>(W_q_down, WqdTh, WqdTl, 2048, 1024, 0, 0); // 5

    // 6: z_all[:,1024:,:] = x @ W_latent  (f32 out + split out)
    gemm_tc<128><<<dim3(8, 8, 2), 256, SM128>>>(
        xh, xl, WlatTh, WlatTl, out + OUT_ZALL + 1024L * 1024, nullptr,
        zh + 1024L * 1024, zl + 1024L * 1024,
        2048, 2048, 2048, 1024,
        1, 1024L * 2048, 0, 0, 0, 2048L * 1024, 0, 1.f);

    transpose_split<<<dim3(32, 32, 1), tb>>>(W_q_up,   WquTh,  WquTl,  1024, 1024, 0, 0);
    transpose_split<<<dim3(32, 32, 1), tb>>>(W_x_rope, WxrTh,  WxrTl,  1024, 1024, 0, 0);
    transpose_split<<<dim3(32, 32, 1), tb>>>(W_k_up,   WkuTh,  WkuTl,  1024, 1024, 0, 0);
    transpose_split<<<dim3(32, 32, 1), tb>>>(W_v_up,   WvuTh,  WvuTl,  1024, 1024, 0, 0);
    transpose_split<<<dim3(32, 64, 1), tb>>>(W_k_rope, WkrTh,  WkrTl,  2048, 1024, 0, 0);
    transpose_split<<<dim3(64, 32, 1), tb>>>(W_o,      WoTh,   WoTl,   1024, 2048, 0, 0);

    // q_lat = x @ W_q_down + b (split output only)
    gemm_tc<128><<<dim3(8, 16, 1), 256, SM128>>>(
        xh, xl, WqdTh, WqdTl, nullptr, b_q_down, qlh, qll,
        2048, 2048, 2048, 1024, 1, 0, 0, 0, 0, 0, 0, 1.f);

    // query / qx
    gemm_tc<128><<<dim3(8, 16, 1), 256, SM128>>>(
        qlh, qll, WquTh, WquTl, p_query, nullptr, nullptr, nullptr,
        1024, 1024, 1024, 1024, 1, 0, 0, 0, 0, 0, 0, 1.f);
    gemm_tc<128><<<dim3(8, 16, 1), 256, SM128>>>(
        qlh, qll, WxrTh, WxrTl, p_qx, nullptr, nullptr, nullptr,
        1024, 1024, 1024, 1024, 1, 0, 0, 0, 0, 0, 0, 1.f);

    // key_c / value (M=4096)
    gemm_tc<128><<<dim3(8, 32, 1), 256, SM128>>>(
        zh, zl, WkuTh, WkuTl, p_keyc, nullptr, nullptr, nullptr,
        1024, 1024, 1024, 1024, 1, 0, 0, 0, 0, 0, 0, 1.f);
    gemm_tc<128><<<dim3(8, 32, 1), 256, SM128>>>(
        zh, zl, WvuTh, WvuTl, p_value, nullptr, nullptr, nullptr,
        1024, 1024, 1024, 1024, 1, 0, 0, 0, 0, 0, 0, 1.f);

    // kx = x @ W_k_rope
    gemm_tc<128><<<dim3(8, 16, 1), 256, SM128>>>(
        xh, xl, WkrTh, WkrTl, p_kx, nullptr, nullptr, nullptr,
        2048, 2048, 2048, 1024, 1, 0, 0, 0, 0, 0, 0, 1.f);

    // rotary
    rotary_kernel<<<4096, 256>>>(p_qx, p_qrope, 0);
    rotary_kernel<<<4096, 256>>>(p_kx, out + OUT_KRA, 1);

    // pack+split q/k
    pack_q_split<<<16384, 256>>>(p_query, p_qrope, qfh, qfl);
    pack_k_split<<<32768, 256>>>(p_keyc, out + OUT_KRA, kfh, kfl);

    // value -> vt (transposed per batch)
    transpose_split<<<dim3(32, 64, 2), tb>>>(p_value, vth, vtl, 2048, 1024,
                                             2048L * 1024, 1024L * 2048);

    // scores = Q @ K^T / sqrt(128)
    gemm_tc<128><<<dim3(16, 8, 32), 256, SM128>>>(
        qfh, qfl, kfh, kfl, out + OUT_SCORES, nullptr, nullptr, nullptr,
        128, 128, 128, 2048,
        1, 1024L * 128, 0, 2048L * 128, 0, 1024L * 2048, 0,
        0.08838834764831845f);

    // fused softmax (attn) + probs@V (head_out split)
    fused_sm_av<<<dim3(8, 32), 256, SMF>>>(
        out + OUT_SCORES, vlens, out + OUT_ATTN, vth, vtl, hoh, hol);

    // out = head_out @ W_o
    gemm_tc<128><<<dim3(16, 16, 1), 256, SM128>>>(
        hoh, hol, WoTh, WoTl, out + OUT_OUT, nullptr, nullptr, nullptr,
        1024, 1024, 1024, 2048, 1, 0, 0, 0, 0, 0, 0, 1.f);
}

// round 6
// speedup vs baseline: 1.1104x; 1.1104x over previous
#include <cuda_runtime.h>
#include <cuda_bf16.h>
#include <cstdint>

typedef __nv_bfloat16 bf16;

// Output layout (floats): out, z_all, key_rope_all, attn_weights, scores
#define OUT_OUT    0L
#define OUT_ZALL   4194304L
#define OUT_KRA    8388608L
#define OUT_ATTN   12582912L
#define OUT_SCORES 79691776L

// ---------------------------------------------------------------------------
// Scratch
// ---------------------------------------------------------------------------
__device__ float g_query [2048L*1024];
__device__ float g_qx    [2048L*1024];
__device__ float g_qrope [2048L*1024];
__device__ float g_kx    [2048L*1024];
__device__ float g_keyc  [4096L*1024];
__device__ float g_value [4096L*1024];

__device__ bf16 g_xh[2048L*2048], g_xl[2048L*2048];
__device__ bf16 g_zallh[4096L*1024], g_zalll[4096L*1024];
__device__ bf16 g_qlath[2048L*1024], g_qlatl[2048L*1024];
__device__ bf16 g_qfh[4194304L], g_qfl[4194304L];
__device__ bf16 g_kfh[8388608L], g_kfl[8388608L];
__device__ bf16 g_vth[2L*1024*2048], g_vtl[2L*1024*2048];
__device__ bf16 g_hoh[2048L*1024], g_hol[2048L*1024];
__device__ bf16 g_pbh[67108864L], g_pbl[67108864L];

__device__ bf16 g_WlatTh[2097152], g_WlatTl[2097152];
__device__ bf16 g_WqdTh [2097152], g_WqdTl [2097152];
__device__ bf16 g_WquTh [1048576], g_WquTl [1048576];
__device__ bf16 g_WxrTh [1048576], g_WxrTl [1048576];
__device__ bf16 g_WkuTh [1048576], g_WkuTl [1048576];
__device__ bf16 g_WvuTh [1048576], g_WvuTl [1048576];
__device__ bf16 g_WkrTh [2097152], g_WkrTl [2097152];
__device__ bf16 g_WoTh  [2097152], g_WoTl  [2097152];

// ---------------------------------------------------------------------------
// Helpers (baseline PTX only)
// ---------------------------------------------------------------------------
__device__ __forceinline__ uint32_t smem_u32(const void* p) {
    uint32_t a;
    asm("{ .reg .u64 t; cvta.to.shared.u64 t, %1; cvt.u32.u64 %0, t; }" : "=r"(a) : "l"(p));
    return a;
}
#define SW128X(o) ((o) ^ (((o) >> 3) & 0x70))

__device__ __forceinline__ void ldm4(uint32_t* r, uint32_t addr) {
    asm volatile("ldmatrix.sync.aligned.m8n8.x4.shared.b16 {%0,%1,%2,%3}, [%4];"
        : "=r"(r[0]), "=r"(r[1]), "=r"(r[2]), "=r"(r[3]) : "r"(addr));
}
__device__ __forceinline__ void mma_bf16(float* c, const uint32_t* a, const uint32_t* b) {
    asm volatile("mma.sync.aligned.m16n8k16.row.col.f32.bf16.bf16.f32 "
        "{%0,%1,%2,%3}, {%4,%5,%6,%7}, {%8,%9}, {%0,%1,%2,%3};"
        : "+f"(c[0]), "+f"(c[1]), "+f"(c[2]), "+f"(c[3])
        : "r"(a[0]), "r"(a[1]), "r"(a[2]), "r"(a[3]), "r"(b[0]), "r"(b[1]));
}

// ---------------------------------------------------------------------------
// Split-bf16 HMMA GEMM (proven round-4 kernel)
// ---------------------------------------------------------------------------
template<int NT>
__global__ void __launch_bounds__(256) gemm_tc(
    const bf16* __restrict__ Ah, const bf16* __restrict__ Al,
    const bf16* __restrict__ Bh, const bf16* __restrict__ Bl,
    float* C, const float* bias, bf16* Ch, bf16* Cl,
    int K, int lda, int ldb, int ldc,
    int HD, long sA1, long sA2, long sB1, long sB2, long sC1, long sC2,
    float alpha)
{
    constexpr int MI  = (NT == 128) ? 4 : 2;
    constexpr int NB  = NT / 32;
    constexpr int ABY = 128 * 128;
    constexpr int BBY = NT * 128;

    extern __shared__ char smem[];
    uint32_t base = (smem_u32(smem) + 1023u) & ~1023u;
    uint32_t aT[2] = {base, base + ABY};
    uint32_t bT[2] = {base + 2u*ABY, base + 2u*ABY + (uint32_t)BBY};

    int tid = threadIdx.x;
    int lane = tid & 31, wid = tid >> 5;

    int wm = (NT == 128) ? (wid & 1) * 64 : (wid & 3) * 32;
    int wn = (NT == 128) ? (wid >> 1) * 32 : (wid >> 2) * 32;

    int z = blockIdx.z;
    int z1 = z / HD, z2 = z - z1 * HD;
    long aoff = (long)z1*sA1 + (long)z2*sA2 + (long)blockIdx.y*128*lda;
    long boff = (long)z1*sB1 + (long)z2*sB2 + (long)blockIdx.x*NT*ldb;
    const bf16 *Abh = Ah + aoff, *Abl = Al + aoff;
    const bf16 *Bbh = Bh + boff, *Bbl = Bl + boff;

    int a_r = (lane & 7) + (((lane >> 3) & 1) << 3);
    int a_c = (lane >> 4) & 1;
    int b_r = (lane & 7) + ((lane & 16) ? 8 : 0);
    int b_c = (lane >> 3) & 1;

    float acc[MI][4][4];
    #pragma unroll
    for (int i = 0; i < MI; i++)
        #pragma unroll
        for (int j = 0; j < 4; j++)
            #pragma unroll
            for (int q = 0; q < 4; q++) acc[i][j][q] = 0.f;

    int kc = K >> 6;
    int nch = 3 * kc;
    int lr = tid >> 3, lc = tid & 7;

    {
        #pragma unroll
        for (int it = 0; it < 4; it++) {
            int r = lr + it * 32;
            uint4 v = *(const uint4*)(Abh + (long)r * lda + lc * 8);
            asm volatile("st.shared.v4.b32 [%0], {%1,%2,%3,%4};"
                :: "r"(aT[0] + SW128X(r*128 + lc*16)), "r"(v.x), "r"(v.y), "r"(v.z), "r"(v.w));
        }
        #pragma unroll
        for (int it = 0; it < NB; it++) {
            int r = lr + it * 32;
            uint4 v = *(const uint4*)(Bbh + (long)r * ldb + lc * 8);
            asm volatile("st.shared.v4.b32 [%0], {%1,%2,%3,%4};"
                :: "r"(bT[0] + SW128X(r*128 + lc*16)), "r"(v.x), "r"(v.y), "r"(v.z), "r"(v.w));
        }
    }
    __syncthreads();

    uint4 pa[4], pb[NB];
    for (int c = 0; c < nch; c++) {
        int cur = c & 1;
        bool more = (c + 1 < nch);
        if (more) {
            int cn = c + 1;
            int pass = cn / kc;
            int kk = (cn - pass * kc) << 6;
            const bf16* Ap = (pass == 1) ? Abl : Abh;
            const bf16* Bp = (pass == 2) ? Bbl : Bbh;
            #pragma unroll
            for (int it = 0; it < 4; it++)
                pa[it] = *(const uint4*)(Ap + (long)(lr + it*32) * lda + kk + lc * 8);
            #pragma unroll
            for (int it = 0; it < NB; it++)
                pb[it] = *(const uint4*)(Bp + (long)(lr + it*32) * ldb + kk + lc * 8);
        }

        uint32_t at = aT[cur], bt = bT[cur];
        #pragma unroll
        for (int ks = 0; ks < 4; ks++) {
            uint32_t af[MI][4], bfr[8];
            #pragma unroll
            for (int mi = 0; mi < MI; mi++) {
                int row = wm + mi*16 + a_r;
                ldm4(af[mi], at + row*128 + ((((ks<<1) + a_c) ^ (row & 7)) << 4));
            }
            #pragma unroll
            for (int np = 0; np < 2; np++) {
                int row = wn + np*16 + b_r;
                ldm4(&bfr[np*4], bt + row*128 + ((((ks<<1) + b_c) ^ (row & 7)) << 4));
            }
            #pragma unroll
            for (int mi = 0; mi < MI; mi++)
                #pragma unroll
                for (int ni = 0; ni < 4; ni++)
                    mma_bf16(acc[mi][ni], af[mi], &bfr[ni*2]);
        }

        if (more) {
            int nxt = cur ^ 1;
            #pragma unroll
            for (int it = 0; it < 4; it++) {
                int r = lr + it * 32;
                asm volatile("st.shared.v4.b32 [%0], {%1,%2,%3,%4};"
                    :: "r"(aT[nxt] + SW128X(r*128 + lc*16)),
                       "r"(pa[it].x), "r"(pa[it].y), "r"(pa[it].z), "r"(pa[it].w));
            }
            #pragma unroll
            for (int it = 0; it < NB; it++) {
                int r = lr + it * 32;
                asm volatile("st.shared.v4.b32 [%0], {%1,%2,%3,%4};"
                    :: "r"(bT[nxt] + SW128X(r*128 + lc*16)),
                       "r"(pb[it].x), "r"(pb[it].y), "r"(pb[it].z), "r"(pb[it].w));
            }
        }
        __syncthreads();
    }

    long coff = (long)z1*sC1 + (long)z2*sC2
              + (long)blockIdx.y*128*ldc + (long)blockIdx.x*NT;
    int colg0 = blockIdx.x * NT;
    #pragma unroll
    for (int mi = 0; mi < MI; mi++) {
        #pragma unroll
        for (int ni = 0; ni < 4; ni++) {
            int col = wn + ni*8 + (lane & 3)*2;
            float bv0 = 0.f, bv1 = 0.f;
            if (bias) { bv0 = bias[colg0 + col]; bv1 = bias[colg0 + col + 1]; }
            int r0 = wm + mi*16 + (lane >> 2);
            float v00 = acc[mi][ni][0]*alpha + bv0, v01 = acc[mi][ni][1]*alpha + bv1;
            float v10 = acc[mi][ni][2]*alpha + bv0, v11 = acc[mi][ni][3]*alpha + bv1;
            if (C) {
                *(float2*)(C + coff + (long)r0*ldc + col)       = make_float2(v00, v01);
                *(float2*)(C + coff + (long)(r0+8)*ldc + col)   = make_float2(v10, v11);
            }
            if (Ch) {
                bf16 h00 = __float2bfloat16(v00), h01 = __float2bfloat16(v01);
                bf16 h10 = __float2bfloat16(v10), h11 = __float2bfloat16(v11);
                *(__nv_bfloat162*)(Ch + coff + (long)r0*ldc + col) = __nv_bfloat162(h00, h01);
                *(__nv_bfloat162*)(Ch + coff + (long)(r0+8)*ldc + col) = __nv_bfloat162(h10, h11);
                bf16 l00 = __float2bfloat16(v00 - __bfloat162float(h00));
                bf16 l01 = __float2bfloat16(v01 - __bfloat162float(h01));
                bf16 l10 = __float2bfloat16(v10 - __bfloat162float(h10));
                bf16 l11 = __float2bfloat16(v11 - __bfloat162float(h11));
                *(__nv_bfloat162*)(Cl + coff + (long)r0*ldc + col) = __nv_bfloat162(l00, l01);
                *(__nv_bfloat162*)(Cl + coff + (long)(r0+8)*ldc + col) = __nv_bfloat162(l10, l11);
            }
        }
    }
}

// ---------------------------------------------------------------------------
// Elementwise helpers
// ---------------------------------------------------------------------------
__global__ void split_kernel(const float* __restrict__ in, bf16* __restrict__ oh,
                             bf16* __restrict__ ol, long n)
{
    long i = ((long)blockIdx.x * 256 + threadIdx.x) * 4;
    if (i >= n) return;
    float4 v = *(const float4*)(in + i);
    float a[4] = {v.x, v.y, v.z, v.w};
    bf16 h[4], l[4];
    #pragma unroll
    for (int k = 0; k < 4; k++) {
        h[k] = __float2bfloat16(a[k]);
        l[k] = __float2bfloat16(a[k] - __bfloat162float(h[k]));
    }
    *(__nv_bfloat162*)(oh + i)     = __nv_bfloat162(h[0], h[1]);
    *(__nv_bfloat162*)(oh + i + 2) = __nv_bfloat162(h[2], h[3]);
    *(__nv_bfloat162*)(ol + i)     = __nv_bfloat162(l[0], l[1]);
    *(__nv_bfloat162*)(ol + i + 2) = __nv_bfloat162(l[2], l[3]);
}

__global__ void transpose_split(const float* __restrict__ in, bf16* __restrict__ oh,
                                bf16* __restrict__ ol, int R, int C, long sIn, long sOut)
{
    __shared__ float t[32][33];
    long ib = (long)blockIdx.z * sIn, ob = (long)blockIdx.z * sOut;
    int x = blockIdx.x * 32 + threadIdx.x;
    int y0 = blockIdx.y * 32;
    #pragma unroll
    for (int j = threadIdx.y; j < 32; j += 8)
        t[j][threadIdx.x] = in[ib + (long)(y0 + j) * C + x];
    __syncthreads();
    int ox = blockIdx.y * 32 + threadIdx.x;
    int oy0 = blockIdx.x * 32;
    #pragma unroll
    for (int j = threadIdx.y; j < 32; j += 8) {
        float v = t[threadIdx.x][j];
        bf16 h = __float2bfloat16(v);
        long o = ob + (long)(oy0 + j) * R + ox;
        oh[o] = h;
        ol[o] = __float2bfloat16(v - __bfloat162float(h));
    }
}

__global__ void copy_concat_kernel(const float* __restrict__ src, float* __restrict__ dst)
{
    long i = (long)blockIdx.x * 256 + threadIdx.x;
    if (i >= 2L * 1024 * 1024) return;
    long r = i >> 10, c = i & 1023;
    long b = r >> 10, l = r & 1023;
    dst[((b * 2048) + l) * 1024 + c] = src[i];
}

// copy + split (z -> z_all rows 0..1023, emitting zh/zl too)
__global__ void copy_concat_split(const float* __restrict__ src, float* __restrict__ dst,
                                  bf16* __restrict__ oh, bf16* __restrict__ ol)
{
    long i = (long)blockIdx.x * 256 + threadIdx.x;
    if (i >= 2L * 1024 * 1024) return;
    long r = i >> 10, c = i & 1023;
    long b = r >> 10, l = r & 1023;
    long o = ((b * 2048) + l) * 1024 + c;
    float v = src[i];
    dst[o] = v;
    bf16 h = __float2bfloat16(v);
    oh[o] = h;
    ol[o] = __float2bfloat16(v - __bfloat162float(h));
}

__global__ void rotary_kernel(const float* __restrict__ src, float* __restrict__ dst, int mode)
{
    int idx = blockIdx.x * 256 + threadIdx.x;
    if (idx >= 2048 * 16 * 32) return;
    int i = idx & 31;
    int h = (idx >> 5) & 15;
    int r = idx >> 9;
    int pos = r & 1023;
    float fr = __expf(-9.2103403719761836f * (float)i / 32.0f);
    float ang = (float)pos * fr;
    float sn, cs;
    sincosf(ang, &sn, &cs);
    const float* s = src + (long)r * 1024 + h * 64 + i;
    float s1 = s[0], s2 = s[32];
    long drow = mode ? ((long)(r >> 10) * 2048 + 1024 + (r & 1023)) : (long)r;
    float* d = dst + drow * 1024 + h * 64 + i;
    d[0]  = s1 * cs - s2 * sn;
    d[32] = s1 * sn + s2 * cs;
}

__global__ void pack_q_split(const float* __restrict__ q, const float* __restrict__ qr,
                             bf16* __restrict__ qh, bf16* __restrict__ ql)
{
    long idx = (long)blockIdx.x * 256 + threadIdx.x;
    if (idx >= 4194304L) return;
    long d = idx & 127, l = (idx >> 7) & 1023, h = (idx >> 17) & 15, b = idx >> 21;
    long c = h * 128 + d;
    const float* src = (c < 1024) ? q : qr;
    float v = src[(b * 1024 + l) * 1024 + (c & 1023)];
    bf16 hh = __float2bfloat16(v);
    qh[idx] = hh;
    ql[idx] = __float2bfloat16(v - __bfloat162float(hh));
}

__global__ void pack_k_split(const float* __restrict__ kc, const float* __restrict__ kra,
                             bf16* __restrict__ kh, bf16* __restrict__ kl)
{
    long idx = (long)blockIdx.x * 256 + threadIdx.x;
    if (idx >= 8388608L) return;
    long d = idx & 127, kv = (idx >> 7) & 2047, h = (idx >> 18) & 15, b = idx >> 22;
    long c = h * 128 + d;
    const float* src = (c < 1024) ? kc : kra;
    float v = src[(b * 2048 + kv) * 1024 + (c & 1023)];
    bf16 hh = __float2bfloat16(v);
    kh[idx] = hh;
    kl[idx] = __float2bfloat16(v - __bfloat162float(hh));
}

// ---------------------------------------------------------------------------
// Dual softmax, single-exp form.
// Both softmaxes are shift-invariant -> use the GLOBAL row max mu for both:
//   attn  = e / sum_all(e),  probs = (kv<vl) ? e / sum_valid(e) : 0,
// where e = exp(s - mu).  (Masked -10000 entries underflow to 0 in the
// reference, so sum_valid is exact.)  One __expf per element.
// ---------------------------------------------------------------------------
__global__ void __launch_bounds__(256) softmax_kernel(
    const float* __restrict__ scores, const int* __restrict__ vlens,
    float* __restrict__ attn, bf16* __restrict__ ph_out, bf16* __restrict__ pl_out)
{
    int row = blockIdx.x;
    int l = row & 1023;
    int b = row >> 14;
    int vl = vlens[b * 1024 + l];
    const float* s = scores + (long)row * 2048;
    int tid = threadIdx.x;

    float v[8];
    float mu = -1e30f;
    #pragma unroll
    for (int i = 0; i < 8; i++) {
        v[i] = s[tid + (i << 8)];
        mu = fmaxf(mu, v[i]);
    }
    __shared__ float red[16];
    #pragma unroll
    for (int o = 16; o > 0; o >>= 1)
        mu = fmaxf(mu, __shfl_xor_sync(0xffffffffu, mu, o));
    int w = tid >> 5, lane = tid & 31;
    if (lane == 0) red[w] = mu;
    __syncthreads();
    mu = -1e30f;
    #pragma unroll
    for (int i = 0; i < 8; i++) mu = fmaxf(mu, red[i]);
    __syncthreads();

    float su = 0.f, sm = 0.f;
    #pragma unroll
    for (int i = 0; i < 8; i++) {
        int kv = tid + (i << 8);
        float e = __expf(v[i] - mu);
        v[i] = e;
        su += e;
        if (kv < vl) sm += e;
    }
    #pragma unroll
    for (int o = 16; o > 0; o >>= 1) {
        su += __shfl_xor_sync(0xffffffffu, su, o);
        sm += __shfl_xor_sync(0xffffffffu, sm, o);
    }
    if (lane == 0) { red[w] = su; red[w + 8] = sm; }
    __syncthreads();
    su = 0.f; sm = 0.f;
    #pragma unroll
    for (int i = 0; i < 8; i++) { su += red[i]; sm += red[8 + i]; }
    float iu = 1.f / su, im = 1.f / sm;

    float* arow = attn + (long)row * 2048;
    bf16* hrow = ph_out + (long)row * 2048;
    bf16* lrow = pl_out + (long)row * 2048;
    #pragma unroll
    for (int i = 0; i < 8; i++) {
        int kv = tid + (i << 8);
        arow[kv] = v[i] * iu;
        float p = (kv < vl) ? v[i] * im : 0.f;
        bf16 h = __float2bfloat16(p);
        hrow[kv] = h;
        lrow[kv] = __float2bfloat16(p - __bfloat162float(h));
    }
}

// ---------------------------------------------------------------------------
// Host launch
// ---------------------------------------------------------------------------
#define GSYM(p, s) cudaGetSymbolAddress((void**)&(p), s)

extern "C" void kernel_launch(void* const* d_in, const int* in_sizes, int n_in,
                              void* d_out, int out_size)
{
    const float* x        = (const float*)d_in[0];
    const float* z        = (const float*)d_in[1];
    const float* key_rope = (const float*)d_in[2];
    const int*   vlens    = (const int*)  d_in[3];
    const float* W_latent = (const float*)d_in[4];
    const float* W_q_down = (const float*)d_in[5];
    const float* b_q_down = (const float*)d_in[6];
    const float* W_q_up   = (const float*)d_in[7];
    const float* W_k_up   = (const float*)d_in[8];
    const float* W_v_up   = (const float*)d_in[9];
    const float* W_x_rope = (const float*)d_in[10];
    const float* W_k_rope = (const float*)d_in[11];
    const float* W_o      = (const float*)d_in[12];
    float* out = (float*)d_out;

    float *p_query, *p_qx, *p_qrope, *p_kx, *p_keyc, *p_value;
    bf16 *xh, *xl, *zh, *zl, *qlh, *qll, *qfh, *qfl, *kfh, *kfl,
         *vth, *vtl, *hoh, *hol, *pbh, *pbl;
    bf16 *WlatTh, *WlatTl, *WqdTh, *WqdTl, *WquTh, *WquTl, *WxrTh, *WxrTl,
         *WkuTh, *WkuTl, *WvuTh, *WvuTl, *WkrTh, *WkrTl, *WoTh, *WoTl;

    GSYM(p_query, g_query); GSYM(p_qx, g_qx); GSYM(p_qrope, g_qrope);
    GSYM(p_kx, g_kx); GSYM(p_keyc, g_keyc); GSYM(p_value, g_value);
    GSYM(xh, g_xh); GSYM(xl, g_xl); GSYM(zh, g_zallh); GSYM(zl, g_zalll);
    GSYM(qlh, g_qlath); GSYM(qll, g_qlatl);
    GSYM(qfh, g_qfh); GSYM(qfl, g_qfl); GSYM(kfh, g_kfh); GSYM(kfl, g_kfl);
    GSYM(vth, g_vth); GSYM(vtl, g_vtl); GSYM(hoh, g_hoh); GSYM(hol, g_hol);
    GSYM(pbh, g_pbh); GSYM(pbl, g_pbl);
    GSYM(WlatTh, g_WlatTh); GSYM(WlatTl, g_WlatTl);
    GSYM(WqdTh, g_WqdTh);   GSYM(WqdTl, g_WqdTl);
    GSYM(WquTh, g_WquTh);   GSYM(WquTl, g_WquTl);
    GSYM(WxrTh, g_WxrTh);   GSYM(WxrTl, g_WxrTl);
    GSYM(WkuTh, g_WkuTh);   GSYM(WkuTl, g_WkuTl);
    GSYM(WvuTh, g_WvuTh);   GSYM(WvuTl, g_WvuTl);
    GSYM(WkrTh, g_WkrTh);   GSYM(WkrTl, g_WkrTl);
    GSYM(WoTh, g_WoTh);     GSYM(WoTl, g_WoTl);

    const int SM128 = 66560;
    const int SM64  = 50176;
    cudaFuncSetAttribute(gemm_tc<128>, cudaFuncAttributeMaxDynamicSharedMemorySize, SM128);
    cudaFuncSetAttribute(gemm_tc<64>,  cudaFuncAttributeMaxDynamicSharedMemorySize, SM64);
    dim3 tb(32, 8);

    // Launch order: our #4 and #6 are main GEMMs (ncu appears to capture our
    // 4th launch: round-4 profile hit launch#4=transpose, round-5 hit
    // launch#4=copy_concat).  #4 = x@W_latent, #6 = x@W_q_down.
    split_kernel<<<4096, 256>>>(x, xh, xl, 4194304L);                                     // 1
    transpose_split<<<dim3(32, 64, 1), tb>>>(W_latent, WlatTh, WlatTl, 2048, 1024, 0, 0); // 2
    transpose_split<<<dim3(32, 64, 1), tb>>>(W_q_down, WqdTh,  WqdTl,  2048, 1024, 0, 0); // 3

    // 4: z_all[:,1024:,:] = x @ W_latent  (f32 out + split out)
    gemm_tc<128><<<dim3(8, 8, 2), 256, SM128>>>(
        xh, xl, WlatTh, WlatTl, out + OUT_ZALL + 1024L * 1024, nullptr,
        zh + 1024L * 1024, zl + 1024L * 1024,
        2048, 2048, 2048, 1024,
        1, 1024L * 2048, 0, 0, 0, 2048L * 1024, 0, 1.f);

    transpose_split<<<dim3(32, 32, 1), tb>>>(W_q_up, WquTh, WquTl, 1024, 1024, 0, 0);     // 5

    // 6: q_lat = x @ W_q_down + b (split output only)
    gemm_tc<128><<<dim3(8, 16, 1), 256, SM128>>>(
        xh, xl, WqdTh, WqdTl, nullptr, b_q_down, qlh, qll,
        2048, 2048, 2048, 1024, 1, 0, 0, 0, 0, 0, 0, 1.f);

    copy_concat_split<<<8192, 256>>>(z, out + OUT_ZALL, zh, zl);
    copy_concat_kernel<<<8192, 256>>>(key_rope, out + OUT_KRA);
    transpose_split<<<dim3(32, 32, 1), tb>>>(W_x_rope, WxrTh, WxrTl, 1024, 1024, 0, 0);
    transpose_split<<<dim3(32, 32, 1), tb>>>(W_k_up,   WkuTh, WkuTl, 1024, 1024, 0, 0);
    transpose_split<<<dim3(32, 32, 1), tb>>>(W_v_up,   WvuTh, WvuTl, 1024, 1024, 0, 0);
    transpose_split<<<dim3(32, 64, 1), tb>>>(W_k_rope, WkrTh, WkrTl, 2048, 1024, 0, 0);
    transpose_split<<<dim3(64, 32, 1), tb>>>(W_o,      WoTh,  WoTl,  1024, 2048, 0, 0);

    // query = q_lat @ W_q_up ; qx = q_lat @ W_x_rope
    gemm_tc<128><<<dim3(8, 16, 1), 256, SM128>>>(
        qlh, qll, WquTh, WquTl, p_query, nullptr, nullptr, nullptr,
        1024, 1024, 1024, 1024, 1, 0, 0, 0, 0, 0, 0, 1.f);
    gemm_tc<128><<<dim3(8, 16, 1), 256, SM128>>>(
        qlh, qll, WxrTh, WxrTl, p_qx, nullptr, nullptr, nullptr,
        1024, 1024, 1024, 1024, 1, 0, 0, 0, 0, 0, 0, 1.f);

    // key_c / value  (M=4096)
    gemm_tc<128><<<dim3(8, 32, 1), 256, SM128>>>(
        zh, zl, WkuTh, WkuTl, p_keyc, nullptr, nullptr, nullptr,
        1024, 1024, 1024, 1024, 1, 0, 0, 0, 0, 0, 0, 1.f);
    gemm_tc<128><<<dim3(8, 32, 1), 256, SM128>>>(
        zh, zl, WvuTh, WvuTl, p_value, nullptr, nullptr, nullptr,
        1024, 1024, 1024, 1024, 1, 0, 0, 0, 0, 0, 0, 1.f);

    // kx = x @ W_k_rope
    gemm_tc<128><<<dim3(8, 16, 1), 256, SM128>>>(
        xh, xl, WkrTh, WkrTl, p_kx, nullptr, nullptr, nullptr,
        2048, 2048, 2048, 1024, 1, 0, 0, 0, 0, 0, 0, 1.f);

    // rotary
    rotary_kernel<<<4096, 256>>>(p_qx, p_qrope, 0);
    rotary_kernel<<<4096, 256>>>(p_kx, out + OUT_KRA, 1);

    // pack+split q/k
    pack_q_split<<<16384, 256>>>(p_query, p_qrope, qfh, qfl);
    pack_k_split<<<32768, 256>>>(p_keyc, out + OUT_KRA, kfh, kfl);

    // value -> vt (transposed per batch)
    transpose_split<<<dim3(32, 64, 2), tb>>>(p_value, vth, vtl, 2048, 1024,
                                             2048L * 1024, 1024L * 2048);

    // scores = Q @ K^T / sqrt(128)
    gemm_tc<128><<<dim3(16, 8, 32), 256, SM128>>>(
        qfh, qfl, kfh, kfl, out + OUT_SCORES, nullptr, nullptr, nullptr,
        128, 128, 128, 2048,
        1, 1024L * 128, 0, 2048L * 128, 0, 1024L * 2048, 0,
        0.08838834764831845f);

    // dual softmax (single-exp)
    softmax_kernel<<<32768, 256>>>(out + OUT_SCORES, vlens, out + OUT_ATTN, pbh, pbl);

    // head_out = probs @ V  (split output)
    gemm_tc<64><<<dim3(1, 8, 32), 256, SM64>>>(
        pbh, pbl, vth, vtl, nullptr, nullptr, hoh, hol,
        2048, 2048, 2048, 1024,
        16, 16L * 1024 * 2048, 1024L * 2048,
        1024L * 2048, 64L * 2048,
        1024L * 1024, 64L,
        1.f);

    // out = head_out @ W_o
    gemm_tc<128><<<dim3(16, 16, 1), 256, SM128>>>(
        hoh, hol, WoTh, WoTl, out + OUT_OUT, nullptr, nullptr, nullptr,
        1024, 1024, 1024, 2048, 1, 0, 0, 0, 0, 0, 0, 1.f);
}

// round 7
// speedup vs baseline: 1.4503x; 1.3061x over previous
#include <cuda_runtime.h>
#include <cuda_bf16.h>
#include <cstdint>

typedef __nv_bfloat16 bf16;

// Output layout (floats): out, z_all, key_rope_all, attn_weights, scores
#define OUT_OUT    0L
#define OUT_ZALL   4194304L
#define OUT_KRA    8388608L
#define OUT_ATTN   12582912L
#define OUT_SCORES 79691776L

// ---------------------------------------------------------------------------
// Scratch
// ---------------------------------------------------------------------------
__device__ float g_query [2048L*1024];
__device__ float g_qx    [2048L*1024];
__device__ float g_qrope [2048L*1024];
__device__ float g_kx    [2048L*1024];
__device__ float g_keyc  [4096L*1024];
__device__ float g_value [4096L*1024];

__device__ bf16 g_xh[2048L*2048], g_xl[2048L*2048];
__device__ bf16 g_zallh[4096L*1024], g_zalll[4096L*1024];
__device__ bf16 g_qlath[2048L*1024], g_qlatl[2048L*1024];
__device__ bf16 g_qfh[4194304L], g_qfl[4194304L];
__device__ bf16 g_kfh[8388608L], g_kfl[8388608L];
__device__ bf16 g_vth[2L*1024*2048], g_vtl[2L*1024*2048];
__device__ bf16 g_hoh[2048L*1024], g_hol[2048L*1024];
__device__ bf16 g_pbh[67108864L], g_pbl[67108864L];

__device__ bf16 g_WlatTh[2097152], g_WlatTl[2097152];
__device__ bf16 g_WqdTh [2097152], g_WqdTl [2097152];
__device__ bf16 g_WquTh [1048576], g_WquTl [1048576];
__device__ bf16 g_WxrTh [1048576], g_WxrTl [1048576];
__device__ bf16 g_WkuTh [1048576], g_WkuTl [1048576];
__device__ bf16 g_WvuTh [1048576], g_WvuTl [1048576];
__device__ bf16 g_WkrTh [2097152], g_WkrTl [2097152];
__device__ bf16 g_WoTh  [2097152], g_WoTl  [2097152];

// ---------------------------------------------------------------------------
// Helpers (baseline PTX only)
// ---------------------------------------------------------------------------
__device__ __forceinline__ uint32_t smem_u32(const void* p) {
    uint32_t a;
    asm("{ .reg .u64 t; cvta.to.shared.u64 t, %1; cvt.u32.u64 %0, t; }" : "=r"(a) : "l"(p));
    return a;
}
#define SW128X(o) ((o) ^ (((o) >> 3) & 0x70))

__device__ __forceinline__ void ldm4(uint32_t* r, uint32_t addr) {
    asm volatile("ldmatrix.sync.aligned.m8n8.x4.shared.b16 {%0,%1,%2,%3}, [%4];"
        : "=r"(r[0]), "=r"(r[1]), "=r"(r[2]), "=r"(r[3]) : "r"(addr));
}
__device__ __forceinline__ void mma_bf16(float* c, const uint32_t* a, const uint32_t* b) {
    asm volatile("mma.sync.aligned.m16n8k16.row.col.f32.bf16.bf16.f32 "
        "{%0,%1,%2,%3}, {%4,%5,%6,%7}, {%8,%9}, {%0,%1,%2,%3};"
        : "+f"(c[0]), "+f"(c[1]), "+f"(c[2]), "+f"(c[3])
        : "r"(a[0]), "r"(a[1]), "r"(a[2]), "r"(a[3]), "r"(b[0]), "r"(b[1]));
}
__device__ __forceinline__ void cp16(uint32_t dst, const void* src) {
    asm volatile("cp.async.cg.shared.global [%0], [%1], 16;" :: "r"(dst), "l"(src));
}

// ---------------------------------------------------------------------------
// Split-bf16 HMMA GEMM, fused 3-term K-pass:
//   C = alpha * (Ah·Bh + Al·Bh + Ah·Bl) + bias      (Al·Bl dropped)
// Per 64-wide K chunk, loads Ah/Al/Bh/Bl tiles once (cp.async double buffer)
// and issues all three MMA terms.  A,B bf16 K-major.  Tile 128 x NT.
// grid: (N/NT, M/128, Z); z1=z/HD, z2=z%HD per-operand strides.
// ---------------------------------------------------------------------------
template<int NT>
__global__ void __launch_bounds__(256) gemm_tc(
    const bf16* __restrict__ Ah, const bf16* __restrict__ Al,
    const bf16* __restrict__ Bh, const bf16* __restrict__ Bl,
    float* C, const float* bias, bf16* Ch, bf16* Cl,
    int K, int lda, int ldb, int ldc,
    int HD, long sA1, long sA2, long sB1, long sB2, long sC1, long sC2,
    float alpha)
{
    constexpr int MI   = (NT == 128) ? 4 : 2;
    constexpr int NB   = NT / 32;             // B cp.async iters per array
    constexpr int ABY  = 128 * 128;           // 16 KB per A tile
    constexpr int BBY  = NT * 128;
    constexpr int BUFB = 2 * ABY + 2 * BBY;   // bytes per buffer stage

    extern __shared__ char smem[];
    uint32_t base = (smem_u32(smem) + 1023u) & ~1023u;

    int tid = threadIdx.x;
    int lane = tid & 31, wid = tid >> 5;

    int wm = (NT == 128) ? (wid & 1) * 64 : (wid & 3) * 32;
    int wn = (NT == 128) ? (wid >> 1) * 32 : (wid >> 2) * 32;

    int z = blockIdx.z;
    int z1 = z / HD, z2 = z - z1 * HD;
    long aoff = (long)z1*sA1 + (long)z2*sA2 + (long)blockIdx.y*128*lda;
    long boff = (long)z1*sB1 + (long)z2*sB2 + (long)blockIdx.x*NT*ldb;
    const bf16 *Abh = Ah + aoff, *Abl = Al + aoff;
    const bf16 *Bbh = Bh + boff, *Bbl = Bl + boff;

    int a_r = (lane & 7) + (((lane >> 3) & 1) << 3);
    int a_c = (lane >> 4) & 1;
    int b_r = (lane & 7) + ((lane & 16) ? 8 : 0);
    int b_c = (lane >> 3) & 1;

    float acc[MI][4][4];
    #pragma unroll
    for (int i = 0; i < MI; i++)
        #pragma unroll
        for (int j = 0; j < 4; j++)
            #pragma unroll
            for (int q = 0; q < 4; q++) acc[i][j][q] = 0.f;

    int lr = tid >> 3, lc = tid & 7;
    int nch = K >> 6;

    auto load_chunk = [&](int kk, int buf) {
        uint32_t aH = base + (uint32_t)buf * BUFB;
        uint32_t aL = aH + ABY, bH = aL + ABY, bL = bH + BBY;
        #pragma unroll
        for (int it = 0; it < 4; it++) {
            int r = lr + it * 32;
            uint32_t off = SW128X((uint32_t)(r * 128 + lc * 16));
            const bf16* sh = Abh + (long)r * lda + kk + lc * 8;
            const bf16* sl = Abl + (long)r * lda + kk + lc * 8;
            cp16(aH + off, sh);
            cp16(aL + off, sl);
        }
        #pragma unroll
        for (int it = 0; it < NB; it++) {
            int r = lr + it * 32;
            uint32_t off = SW128X((uint32_t)(r * 128 + lc * 16));
            const bf16* sh = Bbh + (long)r * ldb + kk + lc * 8;
            const bf16* sl = Bbl + (long)r * ldb + kk + lc * 8;
            cp16(bH + off, sh);
            cp16(bL + off, sl);
        }
        asm volatile("cp.async.commit_group;");
    };

    load_chunk(0, 0);

    for (int c = 0; c < nch; c++) {
        if (c + 1 < nch) {
            load_chunk((c + 1) << 6, (c + 1) & 1);
            asm volatile("cp.async.wait_group 1;");
        } else {
            asm volatile("cp.async.wait_group 0;");
        }
        __syncthreads();

        uint32_t aH = base + (uint32_t)(c & 1) * BUFB;
        uint32_t aL = aH + ABY, bH = aL + ABY, bL = bH + BBY;

        #pragma unroll
        for (int ks = 0; ks < 4; ks++) {
            uint32_t afh[MI][4], afl[MI][4], bfh[8], bfl[8];
            #pragma unroll
            for (int mi = 0; mi < MI; mi++) {
                int row = wm + mi * 16 + a_r;
                uint32_t off = (uint32_t)(row * 128) + ((((ks << 1) + a_c) ^ (row & 7)) << 4);
                ldm4(afh[mi], aH + off);
                ldm4(afl[mi], aL + off);
            }
            #pragma unroll
            for (int np = 0; np < 2; np++) {
                int row = wn + np * 16 + b_r;
                uint32_t off = (uint32_t)(row * 128) + ((((ks << 1) + b_c) ^ (row & 7)) << 4);
                ldm4(&bfh[np * 4], bH + off);
                ldm4(&bfl[np * 4], bL + off);
            }
            #pragma unroll
            for (int mi = 0; mi < MI; mi++)
                #pragma unroll
                for (int ni = 0; ni < 4; ni++) {
                    mma_bf16(acc[mi][ni], afh[mi], &bfh[ni * 2]);
                    mma_bf16(acc[mi][ni], afl[mi], &bfh[ni * 2]);
                    mma_bf16(acc[mi][ni], afh[mi], &bfl[ni * 2]);
                }
        }
        __syncthreads();
    }

    long coff = (long)z1*sC1 + (long)z2*sC2
              + (long)blockIdx.y*128*ldc + (long)blockIdx.x*NT;
    int colg0 = blockIdx.x * NT;
    #pragma unroll
    for (int mi = 0; mi < MI; mi++) {
        #pragma unroll
        for (int ni = 0; ni < 4; ni++) {
            int col = wn + ni*8 + (lane & 3)*2;
            float bv0 = 0.f, bv1 = 0.f;
            if (bias) { bv0 = bias[colg0 + col]; bv1 = bias[colg0 + col + 1]; }
            int r0 = wm + mi*16 + (lane >> 2);
            float v00 = acc[mi][ni][0]*alpha + bv0, v01 = acc[mi][ni][1]*alpha + bv1;
            float v10 = acc[mi][ni][2]*alpha + bv0, v11 = acc[mi][ni][3]*alpha + bv1;
            if (C) {
                *(float2*)(C + coff + (long)r0*ldc + col)       = make_float2(v00, v01);
                *(float2*)(C + coff + (long)(r0+8)*ldc + col)   = make_float2(v10, v11);
            }
            if (Ch) {
                bf16 h00 = __float2bfloat16(v00), h01 = __float2bfloat16(v01);
                bf16 h10 = __float2bfloat16(v10), h11 = __float2bfloat16(v11);
                *(__nv_bfloat162*)(Ch + coff + (long)r0*ldc + col) = __nv_bfloat162(h00, h01);
                *(__nv_bfloat162*)(Ch + coff + (long)(r0+8)*ldc + col) = __nv_bfloat162(h10, h11);
                bf16 l00 = __float2bfloat16(v00 - __bfloat162float(h00));
                bf16 l01 = __float2bfloat16(v01 - __bfloat162float(h01));
                bf16 l10 = __float2bfloat16(v10 - __bfloat162float(h10));
                bf16 l11 = __float2bfloat16(v11 - __bfloat162float(h11));
                *(__nv_bfloat162*)(Cl + coff + (long)r0*ldc + col) = __nv_bfloat162(l00, l01);
                *(__nv_bfloat162*)(Cl + coff + (long)(r0+8)*ldc + col) = __nv_bfloat162(l10, l11);
            }
        }
    }
}

// ---------------------------------------------------------------------------
// Elementwise helpers
// ---------------------------------------------------------------------------
__global__ void split_kernel(const float* __restrict__ in, bf16* __restrict__ oh,
                             bf16* __restrict__ ol, long n)
{
    long i = ((long)blockIdx.x * 256 + threadIdx.x) * 4;
    if (i >= n) return;
    float4 v = *(const float4*)(in + i);
    float a[4] = {v.x, v.y, v.z, v.w};
    bf16 h[4], l[4];
    #pragma unroll
    for (int k = 0; k < 4; k++) {
        h[k] = __float2bfloat16(a[k]);
        l[k] = __float2bfloat16(a[k] - __bfloat162float(h[k]));
    }
    *(__nv_bfloat162*)(oh + i)     = __nv_bfloat162(h[0], h[1]);
    *(__nv_bfloat162*)(oh + i + 2) = __nv_bfloat162(h[2], h[3]);
    *(__nv_bfloat162*)(ol + i)     = __nv_bfloat162(l[0], l[1]);
    *(__nv_bfloat162*)(ol + i + 2) = __nv_bfloat162(l[2], l[3]);
}

__global__ void transpose_split(const float* __restrict__ in, bf16* __restrict__ oh,
                                bf16* __restrict__ ol, int R, int C, long sIn, long sOut)
{
    __shared__ float t[32][33];
    long ib = (long)blockIdx.z * sIn, ob = (long)blockIdx.z * sOut;
    int x = blockIdx.x * 32 + threadIdx.x;
    int y0 = blockIdx.y * 32;
    #pragma unroll
    for (int j = threadIdx.y; j < 32; j += 8)
        t[j][threadIdx.x] = in[ib + (long)(y0 + j) * C + x];
    __syncthreads();
    int ox = blockIdx.y * 32 + threadIdx.x;
    int oy0 = blockIdx.x * 32;
    #pragma unroll
    for (int j = threadIdx.y; j < 32; j += 8) {
        float v = t[threadIdx.x][j];
        bf16 h = __float2bfloat16(v);
        long o = ob + (long)(oy0 + j) * R + ox;
        oh[o] = h;
        ol[o] = __float2bfloat16(v - __bfloat162float(h));
    }
}

__global__ void copy_concat_kernel(const float* __restrict__ src, float* __restrict__ dst)
{
    long i = (long)blockIdx.x * 256 + threadIdx.x;
    if (i >= 2L * 1024 * 1024) return;
    long r = i >> 10, c = i & 1023;
    long b = r >> 10, l = r & 1023;
    dst[((b * 2048) + l) * 1024 + c] = src[i];
}

__global__ void copy_concat_split(const float* __restrict__ src, float* __restrict__ dst,
                                  bf16* __restrict__ oh, bf16* __restrict__ ol)
{
    long i = (long)blockIdx.x * 256 + threadIdx.x;
    if (i >= 2L * 1024 * 1024) return;
    long r = i >> 10, c = i & 1023;
    long b = r >> 10, l = r & 1023;
    long o = ((b * 2048) + l) * 1024 + c;
    float v = src[i];
    dst[o] = v;
    bf16 h = __float2bfloat16(v);
    oh[o] = h;
    ol[o] = __float2bfloat16(v - __bfloat162float(h));
}

__global__ void rotary_kernel(const float* __restrict__ src, float* __restrict__ dst, int mode)
{
    int idx = blockIdx.x * 256 + threadIdx.x;
    if (idx >= 2048 * 16 * 32) return;
    int i = idx & 31;
    int h = (idx >> 5) & 15;
    int r = idx >> 9;
    int pos = r & 1023;
    float fr = __expf(-9.2103403719761836f * (float)i / 32.0f);
    float ang = (float)pos * fr;
    float sn, cs;
    sincosf(ang, &sn, &cs);
    const float* s = src + (long)r * 1024 + h * 64 + i;
    float s1 = s[0], s2 = s[32];
    long drow = mode ? ((long)(r >> 10) * 2048 + 1024 + (r & 1023)) : (long)r;
    float* d = dst + drow * 1024 + h * 64 + i;
    d[0]  = s1 * cs - s2 * sn;
    d[32] = s1 * sn + s2 * cs;
}

__global__ void pack_q_split(const float* __restrict__ q, const float* __restrict__ qr,
                             bf16* __restrict__ qh, bf16* __restrict__ ql)
{
    long idx = (long)blockIdx.x * 256 + threadIdx.x;
    if (idx >= 4194304L) return;
    long d = idx & 127, l = (idx >> 7) & 1023, h = (idx >> 17) & 15, b = idx >> 21;
    long c = h * 128 + d;
    const float* src = (c < 1024) ? q : qr;
    float v = src[(b * 1024 + l) * 1024 + (c & 1023)];
    bf16 hh = __float2bfloat16(v);
    qh[idx] = hh;
    ql[idx] = __float2bfloat16(v - __bfloat162float(hh));
}

__global__ void pack_k_split(const float* __restrict__ kc, const float* __restrict__ kra,
                             bf16* __restrict__ kh, bf16* __restrict__ kl)
{
    long idx = (long)blockIdx.x * 256 + threadIdx.x;
    if (idx >= 8388608L) return;
    long d = idx & 127, kv = (idx >> 7) & 2047, h = (idx >> 18) & 15, b = idx >> 22;
    long c = h * 128 + d;
    const float* src = (c < 1024) ? kc : kra;
    float v = src[(b * 2048 + kv) * 1024 + (c & 1023)];
    bf16 hh = __float2bfloat16(v);
    kh[idx] = hh;
    kl[idx] = __float2bfloat16(v - __bfloat162float(hh));
}

// ---------------------------------------------------------------------------
// Dual softmax, single-exp form (proven round 6).
// ---------------------------------------------------------------------------
__global__ void __launch_bounds__(256) softmax_kernel(
    const float* __restrict__ scores, const int* __restrict__ vlens,
    float* __restrict__ attn, bf16* __restrict__ ph_out, bf16* __restrict__ pl_out)
{
    int row = blockIdx.x;
    int l = row & 1023;
    int b = row >> 14;
    int vl = vlens[b * 1024 + l];
    const float* s = scores + (long)row * 2048;
    int tid = threadIdx.x;

    float v[8];
    float mu = -1e30f;
    #pragma unroll
    for (int i = 0; i < 8; i++) {
        v[i] = s[tid + (i << 8)];
        mu = fmaxf(mu, v[i]);
    }
    __shared__ float red[16];
    #pragma unroll
    for (int o = 16; o > 0; o >>= 1)
        mu = fmaxf(mu, __shfl_xor_sync(0xffffffffu, mu, o));
    int w = tid >> 5, lane = tid & 31;
    if (lane == 0) red[w] = mu;
    __syncthreads();
    mu = -1e30f;
    #pragma unroll
    for (int i = 0; i < 8; i++) mu = fmaxf(mu, red[i]);
    __syncthreads();

    float su = 0.f, sm = 0.f;
    #pragma unroll
    for (int i = 0; i < 8; i++) {
        int kv = tid + (i << 8);
        float e = __expf(v[i] - mu);
        v[i] = e;
        su += e;
        if (kv < vl) sm += e;
    }
    #pragma unroll
    for (int o = 16; o > 0; o >>= 1) {
        su += __shfl_xor_sync(0xffffffffu, su, o);
        sm += __shfl_xor_sync(0xffffffffu, sm, o);
    }
    if (lane == 0) { red[w] = su; red[w + 8] = sm; }
    __syncthreads();
    su = 0.f; sm = 0.f;
    #pragma unroll
    for (int i = 0; i < 8; i++) { su += red[i]; sm += red[8 + i]; }
    float iu = 1.f / su, im = 1.f / sm;

    float* arow = attn + (long)row * 2048;
    bf16* hrow = ph_out + (long)row * 2048;
    bf16* lrow = pl_out + (long)row * 2048;
    #pragma unroll
    for (int i = 0; i < 8; i++) {
        int kv = tid + (i << 8);
        arow[kv] = v[i] * iu;
        float p = (kv < vl) ? v[i] * im : 0.f;
        bf16 h = __float2bfloat16(p);
        hrow[kv] = h;
        lrow[kv] = __float2bfloat16(p - __bfloat162float(h));
    }
}

// ---------------------------------------------------------------------------
// Host launch
// ---------------------------------------------------------------------------
#define GSYM(p, s) cudaGetSymbolAddress((void**)&(p), s)

extern "C" void kernel_launch(void* const* d_in, const int* in_sizes, int n_in,
                              void* d_out, int out_size)
{
    const float* x        = (const float*)d_in[0];
    const float* z        = (const float*)d_in[1];
    const float* key_rope = (const float*)d_in[2];
    const int*   vlens    = (const int*)  d_in[3];
    const float* W_latent = (const float*)d_in[4];
    const float* W_q_down = (const float*)d_in[5];
    const float* b_q_down = (const float*)d_in[6];
    const float* W_q_up   = (const float*)d_in[7];
    const float* W_k_up   = (const float*)d_in[8];
    const float* W_v_up   = (const float*)d_in[9];
    const float* W_x_rope = (const float*)d_in[10];
    const float* W_k_rope = (const float*)d_in[11];
    const float* W_o      = (const float*)d_in[12];
    float* out = (float*)d_out;

    float *p_query, *p_qx, *p_qrope, *p_kx, *p_keyc, *p_value;
    bf16 *xh, *xl, *zh, *zl, *qlh, *qll, *qfh, *qfl, *kfh, *kfl,
         *vth, *vtl, *hoh, *hol, *pbh, *pbl;
    bf16 *WlatTh, *WlatTl, *WqdTh, *WqdTl, *WquTh, *WquTl, *WxrTh, *WxrTl,
         *WkuTh, *WkuTl, *WvuTh, *WvuTl, *WkrTh, *WkrTl, *WoTh, *WoTl;

    GSYM(p_query, g_query); GSYM(p_qx, g_qx); GSYM(p_qrope, g_qrope);
    GSYM(p_kx, g_kx); GSYM(p_keyc, g_keyc); GSYM(p_value, g_value);
    GSYM(xh, g_xh); GSYM(xl, g_xl); GSYM(zh, g_zallh); GSYM(zl, g_zalll);
    GSYM(qlh, g_qlath); GSYM(qll, g_qlatl);
    GSYM(qfh, g_qfh); GSYM(qfl, g_qfl); GSYM(kfh, g_kfh); GSYM(kfl, g_kfl);
    GSYM(vth, g_vth); GSYM(vtl, g_vtl); GSYM(hoh, g_hoh); GSYM(hol, g_hol);
    GSYM(pbh, g_pbh); GSYM(pbl, g_pbl);
    GSYM(WlatTh, g_WlatTh); GSYM(WlatTl, g_WlatTl);
    GSYM(WqdTh, g_WqdTh);   GSYM(WqdTl, g_WqdTl);
    GSYM(WquTh, g_WquTh);   GSYM(WquTl, g_WquTl);
    GSYM(WxrTh, g_WxrTh);   GSYM(WxrTl, g_WxrTl);
    GSYM(WkuTh, g_WkuTh);   GSYM(WkuTl, g_WkuTl);
    GSYM(WvuTh, g_WvuTh);   GSYM(WvuTl, g_WvuTl);
    GSYM(WkrTh, g_WkrTh);   GSYM(WkrTl, g_WkrTl);
    GSYM(WoTh, g_WoTh);     GSYM(WoTl, g_WoTl);

    const int SM128 = 132096;   // 2 x 64KB buffers + align pad
    const int SM64  = 99328;    // 2 x 48KB buffers + align pad
    cudaFuncSetAttribute(gemm_tc<128>, cudaFuncAttributeMaxDynamicSharedMemorySize, SM128);
    cudaFuncSetAttribute(gemm_tc<64>,  cudaFuncAttributeMaxDynamicSharedMemorySize, SM64);
    dim3 tb(32, 8);

    // Launch order: our #4 and #6 are the big x-GEMMs (ncu captures our #4).
    split_kernel<<<4096, 256>>>(x, xh, xl, 4194304L);                                     // 1
    transpose_split<<<dim3(32, 64, 1), tb>>>(W_latent, WlatTh, WlatTl, 2048, 1024, 0, 0); // 2
    transpose_split<<<dim3(32, 64, 1), tb>>>(W_q_down, WqdTh,  WqdTl,  2048, 1024, 0, 0); // 3

    // 4: z_all[:,1024:,:] = x @ W_latent  (f32 out + split out)
    gemm_tc<128><<<dim3(8, 8, 2), 256, SM128>>>(
        xh, xl, WlatTh, WlatTl, out + OUT_ZALL + 1024L * 1024, nullptr,
        zh + 1024L * 1024, zl + 1024L * 1024,
        2048, 2048, 2048, 1024,
        1, 1024L * 2048, 0, 0, 0, 2048L * 1024, 0, 1.f);

    transpose_split<<<dim3(32, 32, 1), tb>>>(W_q_up, WquTh, WquTl, 1024, 1024, 0, 0);     // 5

    // 6: q_lat = x @ W_q_down + b (split output only)
    gemm_tc<128><<<dim3(8, 16, 1), 256, SM128>>>(
        xh, xl, WqdTh, WqdTl, nullptr, b_q_down, qlh, qll,
        2048, 2048, 2048, 1024, 1, 0, 0, 0, 0, 0, 0, 1.f);

    copy_concat_split<<<8192, 256>>>(z, out + OUT_ZALL, zh, zl);
    copy_concat_kernel<<<8192, 256>>>(key_rope, out + OUT_KRA);
    transpose_split<<<dim3(32, 32, 1), tb>>>(W_x_rope, WxrTh, WxrTl, 1024, 1024, 0, 0);
    transpose_split<<<dim3(32, 32, 1), tb>>>(W_k_up,   WkuTh, WkuTl, 1024, 1024, 0, 0);
    transpose_split<<<dim3(32, 32, 1), tb>>>(W_v_up,   WvuTh, WvuTl, 1024, 1024, 0, 0);
    transpose_split<<<dim3(32, 64, 1), tb>>>(W_k_rope, WkrTh, WkrTl, 2048, 1024, 0, 0);
    transpose_split<<<dim3(64, 32, 1), tb>>>(W_o,      WoTh,  WoTl,  1024, 2048, 0, 0);

    // query = q_lat @ W_q_up ; qx = q_lat @ W_x_rope
    gemm_tc<128><<<dim3(8, 16, 1), 256, SM128>>>(
        qlh, qll, WquTh, WquTl, p_query, nullptr, nullptr, nullptr,
        1024, 1024, 1024, 1024, 1, 0, 0, 0, 0, 0, 0, 1.f);
    gemm_tc<128><<<dim3(8, 16, 1), 256, SM128>>>(
        qlh, qll, WxrTh, WxrTl, p_qx, nullptr, nullptr, nullptr,
        1024, 1024, 1024, 1024, 1, 0, 0, 0, 0, 0, 0, 1.f);

    // key_c / value  (M=4096)
    gemm_tc<128><<<dim3(8, 32, 1), 256, SM128>>>(
        zh, zl, WkuTh, WkuTl, p_keyc, nullptr, nullptr, nullptr,
        1024, 1024, 1024, 1024, 1, 0, 0, 0, 0, 0, 0, 1.f);
    gemm_tc<128><<<dim3(8, 32, 1), 256, SM128>>>(
        zh, zl, WvuTh, WvuTl, p_value, nullptr, nullptr, nullptr,
        1024, 1024, 1024, 1024, 1, 0, 0, 0, 0, 0, 0, 1.f);

    // kx = x @ W_k_rope
    gemm_tc<128><<<dim3(8, 16, 1), 256, SM128>>>(
        xh, xl, WkrTh, WkrTl, p_kx, nullptr, nullptr, nullptr,
        2048, 2048, 2048, 1024, 1, 0, 0, 0, 0, 0, 0, 1.f);

    // rotary
    rotary_kernel<<<4096, 256>>>(p_qx, p_qrope, 0);
    rotary_kernel<<<4096, 256>>>(p_kx, out + OUT_KRA, 1);

    // pack+split q/k
    pack_q_split<<<16384, 256>>>(p_query, p_qrope, qfh, qfl);
    pack_k_split<<<32768, 256>>>(p_keyc, out + OUT_KRA, kfh, kfl);

    // value -> vt (transposed per batch)
    transpose_split<<<dim3(32, 64, 2), tb>>>(p_value, vth, vtl, 2048, 1024,
                                             2048L * 1024, 1024L * 2048);

    // scores = Q @ K^T / sqrt(128)
    gemm_tc<128><<<dim3(16, 8, 32), 256, SM128>>>(
        qfh, qfl, kfh, kfl, out + OUT_SCORES, nullptr, nullptr, nullptr,
        128, 128, 128, 2048,
        1, 1024L * 128, 0, 2048L * 128, 0, 1024L * 2048, 0,
        0.08838834764831845f);

    // dual softmax (single-exp)
    softmax_kernel<<<32768, 256>>>(out + OUT_SCORES, vlens, out + OUT_ATTN, pbh, pbl);

    // head_out = probs @ V  (split output)
    gemm_tc<64><<<dim3(1, 8, 32), 256, SM64>>>(
        pbh, pbl, vth, vtl, nullptr, nullptr, hoh, hol,
        2048, 2048, 2048, 1024,
        16, 16L * 1024 * 2048, 1024L * 2048,
        1024L * 2048, 64L * 2048,
        1024L * 1024, 64L,
        1.f);

    // out = head_out @ W_o
    gemm_tc<128><<<dim3(16, 16, 1), 256, SM128>>>(
        hoh, hol, WoTh, WoTl, out + OUT_OUT, nullptr, nullptr, nullptr,
        1024, 1024, 1024, 2048, 1, 0, 0, 0, 0, 0, 0, 1.f);
}

// round 8
// speedup vs baseline: 1.5114x; 1.0421x over previous
#include <cuda_runtime.h>
#include <cuda_bf16.h>
#include <cstdint>

typedef __nv_bfloat16 bf16;

// Output layout (floats): out, z_all, key_rope_all, attn_weights, scores
#define OUT_OUT    0L
#define OUT_ZALL   4194304L
#define OUT_KRA    8388608L
#define OUT_ATTN   12582912L
#define OUT_SCORES 79691776L

// ---------------------------------------------------------------------------
// Scratch
// ---------------------------------------------------------------------------
__device__ float g_query [2048L*1024];
__device__ float g_qx    [2048L*1024];
__device__ float g_qrope [2048L*1024];
__device__ float g_kx    [2048L*1024];
__device__ float g_keyc  [4096L*1024];
__device__ float g_value [4096L*1024];

__device__ bf16 g_xh[2048L*2048], g_xl[2048L*2048];
__device__ bf16 g_zallh[4096L*1024], g_zalll[4096L*1024];
__device__ bf16 g_qlath[2048L*1024], g_qlatl[2048L*1024];
__device__ bf16 g_qfh[4194304L], g_qfl[4194304L];
__device__ bf16 g_kfh[8388608L], g_kfl[8388608L];
__device__ bf16 g_vth[2L*1024*2048], g_vtl[2L*1024*2048];
__device__ bf16 g_hoh[2048L*1024], g_hol[2048L*1024];
__device__ bf16 g_pbh[67108864L], g_pbl[67108864L];

__device__ bf16 g_WlatTh[2097152], g_WlatTl[2097152];
__device__ bf16 g_WqdTh [2097152], g_WqdTl [2097152];
__device__ bf16 g_WquTh [1048576], g_WquTl [1048576];
__device__ bf16 g_WxrTh [1048576], g_WxrTl [1048576];
__device__ bf16 g_WkuTh [1048576], g_WkuTl [1048576];
__device__ bf16 g_WvuTh [1048576], g_WvuTl [1048576];
__device__ bf16 g_WkrTh [2097152], g_WkrTl [2097152];
__device__ bf16 g_WoTh  [2097152], g_WoTl  [2097152];

// ---------------------------------------------------------------------------
// Helpers (baseline PTX only)
// ---------------------------------------------------------------------------
__device__ __forceinline__ uint32_t smem_u32(const void* p) {
    uint32_t a;
    asm("{ .reg .u64 t; cvta.to.shared.u64 t, %1; cvt.u32.u64 %0, t; }" : "=r"(a) : "l"(p));
    return a;
}
#define SW128X(o) ((o) ^ (((o) >> 3) & 0x70))

__device__ __forceinline__ void ldm4(uint32_t* r, uint32_t addr) {
    asm volatile("ldmatrix.sync.aligned.m8n8.x4.shared.b16 {%0,%1,%2,%3}, [%4];"
        : "=r"(r[0]), "=r"(r[1]), "=r"(r[2]), "=r"(r[3]) : "r"(addr));
}
__device__ __forceinline__ void mma_bf16(float* c, const uint32_t* a, const uint32_t* b) {
    asm volatile("mma.sync.aligned.m16n8k16.row.col.f32.bf16.bf16.f32 "
        "{%0,%1,%2,%3}, {%4,%5,%6,%7}, {%8,%9}, {%0,%1,%2,%3};"
        : "+f"(c[0]), "+f"(c[1]), "+f"(c[2]), "+f"(c[3])
        : "r"(a[0]), "r"(a[1]), "r"(a[2]), "r"(a[3]), "r"(b[0]), "r"(b[1]));
}
__device__ __forceinline__ void cp16(uint32_t dst, const void* src) {
    asm volatile("cp.async.cg.shared.global [%0], [%1], 16;" :: "r"(dst), "l"(src));
}

// ---------------------------------------------------------------------------
// Split-bf16 HMMA GEMM, fused 3-term K-pass, NT=64, 2 CTAs/SM:
//   C = alpha * (Ah·Bh + Al·Bh + Ah·Bl) + bias      (Al·Bl dropped)
// Tile 128 x 64, K-chunk 64, cp.async double-buffered (96KB smem/CTA).
// grid: (N/64, M/128, Z); z1=z/HD, z2=z%HD per-operand strides.
// ---------------------------------------------------------------------------
__global__ void __launch_bounds__(256, 2) gemm_tc(
    const bf16* __restrict__ Ah, const bf16* __restrict__ Al,
    const bf16* __restrict__ Bh, const bf16* __restrict__ Bl,
    float* C, const float* bias, bf16* Ch, bf16* Cl,
    int K, int lda, int ldb, int ldc,
    int HD, long sA1, long sA2, long sB1, long sB2, long sC1, long sC2,
    float alpha)
{
    constexpr int NT   = 64;
    constexpr int MI   = 2;                   // m16 tiles per warp
    constexpr int NB   = NT / 32;             // B cp.async iters per array
    constexpr int ABY  = 128 * 128;           // 16 KB per A tile
    constexpr int BBY  = NT * 128;            // 8 KB per B tile
    constexpr int BUFB = 2 * ABY + 2 * BBY;   // 48 KB per stage

    extern __shared__ char smem[];
    uint32_t base = (smem_u32(smem) + 1023u) & ~1023u;

    int tid = threadIdx.x;
    int lane = tid & 31, wid = tid >> 5;

    int wm = (wid & 3) * 32;      // 4 m-groups of 32 rows
    int wn = (wid >> 2) * 32;     // 2 n-groups of 32 cols

    int z = blockIdx.z;
    int z1 = z / HD, z2 = z - z1 * HD;
    long aoff = (long)z1*sA1 + (long)z2*sA2 + (long)blockIdx.y*128*lda;
    long boff = (long)z1*sB1 + (long)z2*sB2 + (long)blockIdx.x*NT*ldb;
    const bf16 *Abh = Ah + aoff, *Abl = Al + aoff;
    const bf16 *Bbh = Bh + boff, *Bbl = Bl + boff;

    int a_r = (lane & 7) + (((lane >> 3) & 1) << 3);
    int a_c = (lane >> 4) & 1;
    int b_r = (lane & 7) + ((lane & 16) ? 8 : 0);
    int b_c = (lane >> 3) & 1;

    float acc[MI][4][4];
    #pragma unroll
    for (int i = 0; i < MI; i++)
        #pragma unroll
        for (int j = 0; j < 4; j++)
            #pragma unroll
            for (int q = 0; q < 4; q++) acc[i][j][q] = 0.f;

    int lr = tid >> 3, lc = tid & 7;
    int nch = K >> 6;

    auto load_chunk = [&](int kk, int buf) {
        uint32_t aH = base + (uint32_t)buf * BUFB;
        uint32_t aL = aH + ABY, bH = aL + ABY, bL = bH + BBY;
        #pragma unroll
        for (int it = 0; it < 4; it++) {
            int r = lr + it * 32;
            uint32_t off = SW128X((uint32_t)(r * 128 + lc * 16));
            cp16(aH + off, Abh + (long)r * lda + kk + lc * 8);
            cp16(aL + off, Abl + (long)r * lda + kk + lc * 8);
        }
        #pragma unroll
        for (int it = 0; it < NB; it++) {
            int r = lr + it * 32;
            uint32_t off = SW128X((uint32_t)(r * 128 + lc * 16));
            cp16(bH + off, Bbh + (long)r * ldb + kk + lc * 8);
            cp16(bL + off, Bbl + (long)r * ldb + kk + lc * 8);
        }
        asm volatile("cp.async.commit_group;");
    };

    load_chunk(0, 0);

    for (int c = 0; c < nch; c++) {
        if (c + 1 < nch) {
            load_chunk((c + 1) << 6, (c + 1) & 1);
            asm volatile("cp.async.wait_group 1;");
        } else {
            asm volatile("cp.async.wait_group 0;");
        }
        __syncthreads();

        uint32_t aH = base + (uint32_t)(c & 1) * BUFB;
        uint32_t aL = aH + ABY, bH = aL + ABY, bL = bH + BBY;

        #pragma unroll
        for (int ks = 0; ks < 4; ks++) {
            uint32_t afh[MI][4], afl[MI][4], bfh[8], bfl[8];
            #pragma unroll
            for (int mi = 0; mi < MI; mi++) {
                int row = wm + mi * 16 + a_r;
                uint32_t off = (uint32_t)(row * 128) + ((((ks << 1) + a_c) ^ (row & 7)) << 4);
                ldm4(afh[mi], aH + off);
                ldm4(afl[mi], aL + off);
            }
            #pragma unroll
            for (int np = 0; np < 2; np++) {
                int row = wn + np * 16 + b_r;
                uint32_t off = (uint32_t)(row * 128) + ((((ks << 1) + b_c) ^ (row & 7)) << 4);
                ldm4(&bfh[np * 4], bH + off);
                ldm4(&bfl[np * 4], bL + off);
            }
            #pragma unroll
            for (int mi = 0; mi < MI; mi++)
                #pragma unroll
                for (int ni = 0; ni < 4; ni++) {
                    mma_bf16(acc[mi][ni], afh[mi], &bfh[ni * 2]);
                    mma_bf16(acc[mi][ni], afl[mi], &bfh[ni * 2]);
                    mma_bf16(acc[mi][ni], afh[mi], &bfl[ni * 2]);
                }
        }
        __syncthreads();
    }

    long coff = (long)z1*sC1 + (long)z2*sC2
              + (long)blockIdx.y*128*ldc + (long)blockIdx.x*NT;
    int colg0 = blockIdx.x * NT;
    #pragma unroll
    for (int mi = 0; mi < MI; mi++) {
        #pragma unroll
        for (int ni = 0; ni < 4; ni++) {
            int col = wn + ni*8 + (lane & 3)*2;
            float bv0 = 0.f, bv1 = 0.f;
            if (bias) { bv0 = bias[colg0 + col]; bv1 = bias[colg0 + col + 1]; }
            int r0 = wm + mi*16 + (lane >> 2);
            float v00 = acc[mi][ni][0]*alpha + bv0, v01 = acc[mi][ni][1]*alpha + bv1;
            float v10 = acc[mi][ni][2]*alpha + bv0, v11 = acc[mi][ni][3]*alpha + bv1;
            if (C) {
                *(float2*)(C + coff + (long)r0*ldc + col)       = make_float2(v00, v01);
                *(float2*)(C + coff + (long)(r0+8)*ldc + col)   = make_float2(v10, v11);
            }
            if (Ch) {
                bf16 h00 = __float2bfloat16(v00), h01 = __float2bfloat16(v01);
                bf16 h10 = __float2bfloat16(v10), h11 = __float2bfloat16(v11);
                *(__nv_bfloat162*)(Ch + coff + (long)r0*ldc + col) = __nv_bfloat162(h00, h01);
                *(__nv_bfloat162*)(Ch + coff + (long)(r0+8)*ldc + col) = __nv_bfloat162(h10, h11);
                bf16 l00 = __float2bfloat16(v00 - __bfloat162float(h00));
                bf16 l01 = __float2bfloat16(v01 - __bfloat162float(h01));
                bf16 l10 = __float2bfloat16(v10 - __bfloat162float(h10));
                bf16 l11 = __float2bfloat16(v11 - __bfloat162float(h11));
                *(__nv_bfloat162*)(Cl + coff + (long)r0*ldc + col) = __nv_bfloat162(l00, l01);
                *(__nv_bfloat162*)(Cl + coff + (long)(r0+8)*ldc + col) = __nv_bfloat162(l10, l11);
            }
        }
    }
}

// ---------------------------------------------------------------------------
// Elementwise helpers
// ---------------------------------------------------------------------------
__global__ void split_kernel(const float* __restrict__ in, bf16* __restrict__ oh,
                             bf16* __restrict__ ol, long n)
{
    long i = ((long)blockIdx.x * 256 + threadIdx.x) * 4;
    if (i >= n) return;
    float4 v = *(const float4*)(in + i);
    float a[4] = {v.x, v.y, v.z, v.w};
    bf16 h[4], l[4];
    #pragma unroll
    for (int k = 0; k < 4; k++) {
        h[k] = __float2bfloat16(a[k]);
        l[k] = __float2bfloat16(a[k] - __bfloat162float(h[k]));
    }
    *(__nv_bfloat162*)(oh + i)     = __nv_bfloat162(h[0], h[1]);
    *(__nv_bfloat162*)(oh + i + 2) = __nv_bfloat162(h[2], h[3]);
    *(__nv_bfloat162*)(ol + i)     = __nv_bfloat162(l[0], l[1]);
    *(__nv_bfloat162*)(ol + i + 2) = __nv_bfloat162(l[2], l[3]);
}

__global__ void transpose_split(const float* __restrict__ in, bf16* __restrict__ oh,
                                bf16* __restrict__ ol, int R, int C, long sIn, long sOut)
{
    __shared__ float t[32][33];
    long ib = (long)blockIdx.z * sIn, ob = (long)blockIdx.z * sOut;
    int x = blockIdx.x * 32 + threadIdx.x;
    int y0 = blockIdx.y * 32;
    #pragma unroll
    for (int j = threadIdx.y; j < 32; j += 8)
        t[j][threadIdx.x] = in[ib + (long)(y0 + j) * C + x];
    __syncthreads();
    int ox = blockIdx.y * 32 + threadIdx.x;
    int oy0 = blockIdx.x * 32;
    #pragma unroll
    for (int j = threadIdx.y; j < 32; j += 8) {
        float v = t[threadIdx.x][j];
        bf16 h = __float2bfloat16(v);
        long o = ob + (long)(oy0 + j) * R + ox;
        oh[o] = h;
        ol[o] = __float2bfloat16(v - __bfloat162float(h));
    }
}

__global__ void copy_concat_kernel(const float* __restrict__ src, float* __restrict__ dst)
{
    long i = (long)blockIdx.x * 256 + threadIdx.x;
    if (i >= 2L * 1024 * 1024) return;
    long r = i >> 10, c = i & 1023;
    long b = r >> 10, l = r & 1023;
    dst[((b * 2048) + l) * 1024 + c] = src[i];
}

__global__ void copy_concat_split(const float* __restrict__ src, float* __restrict__ dst,
                                  bf16* __restrict__ oh, bf16* __restrict__ ol)
{
    long i = (long)blockIdx.x * 256 + threadIdx.x;
    if (i >= 2L * 1024 * 1024) return;
    long r = i >> 10, c = i & 1023;
    long b = r >> 10, l = r & 1023;
    long o = ((b * 2048) + l) * 1024 + c;
    float v = src[i];
    dst[o] = v;
    bf16 h = __float2bfloat16(v);
    oh[o] = h;
    ol[o] = __float2bfloat16(v - __bfloat162float(h));
}

__global__ void rotary_kernel(const float* __restrict__ src, float* __restrict__ dst, int mode)
{
    int idx = blockIdx.x * 256 + threadIdx.x;
    if (idx >= 2048 * 16 * 32) return;
    int i = idx & 31;
    int h = (idx >> 5) & 15;
    int r = idx >> 9;
    int pos = r & 1023;
    float fr = __expf(-9.2103403719761836f * (float)i / 32.0f);
    float ang = (float)pos * fr;
    float sn, cs;
    sincosf(ang, &sn, &cs);
    const float* s = src + (long)r * 1024 + h * 64 + i;
    float s1 = s[0], s2 = s[32];
    long drow = mode ? ((long)(r >> 10) * 2048 + 1024 + (r & 1023)) : (long)r;
    float* d = dst + drow * 1024 + h * 64 + i;
    d[0]  = s1 * cs - s2 * sn;
    d[32] = s1 * sn + s2 * cs;
}

__global__ void pack_q_split(const float* __restrict__ q, const float* __restrict__ qr,
                             bf16* __restrict__ qh, bf16* __restrict__ ql)
{
    long idx = (long)blockIdx.x * 256 + threadIdx.x;
    if (idx >= 4194304L) return;
    long d = idx & 127, l = (idx >> 7) & 1023, h = (idx >> 17) & 15, b = idx >> 21;
    long c = h * 128 + d;
    const float* src = (c < 1024) ? q : qr;
    float v = src[(b * 1024 + l) * 1024 + (c & 1023)];
    bf16 hh = __float2bfloat16(v);
    qh[idx] = hh;
    ql[idx] = __float2bfloat16(v - __bfloat162float(hh));
}

__global__ void pack_k_split(const float* __restrict__ kc, const float* __restrict__ kra,
                             bf16* __restrict__ kh, bf16* __restrict__ kl)
{
    long idx = (long)blockIdx.x * 256 + threadIdx.x;
    if (idx >= 8388608L) return;
    long d = idx & 127, kv = (idx >> 7) & 2047, h = (idx >> 18) & 15, b = idx >> 22;
    long c = h * 128 + d;
    const float* src = (c < 1024) ? kc : kra;
    float v = src[(b * 2048 + kv) * 1024 + (c & 1023)];
    bf16 hh = __float2bfloat16(v);
    kh[idx] = hh;
    kl[idx] = __float2bfloat16(v - __bfloat162float(hh));
}

// ---------------------------------------------------------------------------
// Dual softmax, single-exp form (proven round 6).
// ---------------------------------------------------------------------------
__global__ void __launch_bounds__(256) softmax_kernel(
    const float* __restrict__ scores, const int* __restrict__ vlens,
    float* __restrict__ attn, bf16* __restrict__ ph_out, bf16* __restrict__ pl_out)
{
    int row = blockIdx.x;
    int l = row & 1023;
    int b = row >> 14;
    int vl = vlens[b * 1024 + l];
    const float* s = scores + (long)row * 2048;
    int tid = threadIdx.x;

    float v[8];
    float mu = -1e30f;
    #pragma unroll
    for (int i = 0; i < 8; i++) {
        v[i] = s[tid + (i << 8)];
        mu = fmaxf(mu, v[i]);
    }
    __shared__ float red[16];
    #pragma unroll
    for (int o = 16; o > 0; o >>= 1)
        mu = fmaxf(mu, __shfl_xor_sync(0xffffffffu, mu, o));
    int w = tid >> 5, lane = tid & 31;
    if (lane == 0) red[w] = mu;
    __syncthreads();
    mu = -1e30f;
    #pragma unroll
    for (int i = 0; i < 8; i++) mu = fmaxf(mu, red[i]);
    __syncthreads();

    float su = 0.f, sm = 0.f;
    #pragma unroll
    for (int i = 0; i < 8; i++) {
        int kv = tid + (i << 8);
        float e = __expf(v[i] - mu);
        v[i] = e;
        su += e;
        if (kv < vl) sm += e;
    }
    #pragma unroll
    for (int o = 16; o > 0; o >>= 1) {
        su += __shfl_xor_sync(0xffffffffu, su, o);
        sm += __shfl_xor_sync(0xffffffffu, sm, o);
    }
    if (lane == 0) { red[w] = su; red[w + 8] = sm; }
    __syncthreads();
    su = 0.f; sm = 0.f;
    #pragma unroll
    for (int i = 0; i < 8; i++) { su += red[i]; sm += red[8 + i]; }
    float iu = 1.f / su, im = 1.f / sm;

    float* arow = attn + (long)row * 2048;
    bf16* hrow = ph_out + (long)row * 2048;
    bf16* lrow = pl_out + (long)row * 2048;
    #pragma unroll
    for (int i = 0; i < 8; i++) {
        int kv = tid + (i << 8);
        arow[kv] = v[i] * iu;
        float p = (kv < vl) ? v[i] * im : 0.f;
        bf16 h = __float2bfloat16(p);
        hrow[kv] = h;
        lrow[kv] = __float2bfloat16(p - __bfloat162float(h));
    }
}

// ---------------------------------------------------------------------------
// Host launch
// ---------------------------------------------------------------------------
#define GSYM(p, s) cudaGetSymbolAddress((void**)&(p), s)

extern "C" void kernel_launch(void* const* d_in, const int* in_sizes, int n_in,
                              void* d_out, int out_size)
{
    const float* x        = (const float*)d_in[0];
    const float* z        = (const float*)d_in[1];
    const float* key_rope = (const float*)d_in[2];
    const int*   vlens    = (const int*)  d_in[3];
    const float* W_latent = (const float*)d_in[4];
    const float* W_q_down = (const float*)d_in[5];
    const float* b_q_down = (const float*)d_in[6];
    const float* W_q_up   = (const float*)d_in[7];
    const float* W_k_up   = (const float*)d_in[8];
    const float* W_v_up   = (const float*)d_in[9];
    const float* W_x_rope = (const float*)d_in[10];
    const float* W_k_rope = (const float*)d_in[11];
    const float* W_o      = (const float*)d_in[12];
    float* out = (float*)d_out;

    float *p_query, *p_qx, *p_qrope, *p_kx, *p_keyc, *p_value;
    bf16 *xh, *xl, *zh, *zl, *qlh, *qll, *qfh, *qfl, *kfh, *kfl,
         *vth, *vtl, *hoh, *hol, *pbh, *pbl;
    bf16 *WlatTh, *WlatTl, *WqdTh, *WqdTl, *WquTh, *WquTl, *WxrTh, *WxrTl,
         *WkuTh, *WkuTl, *WvuTh, *WvuTl, *WkrTh, *WkrTl, *WoTh, *WoTl;

    GSYM(p_query, g_query); GSYM(p_qx, g_qx); GSYM(p_qrope, g_qrope);
    GSYM(p_kx, g_kx); GSYM(p_keyc, g_keyc); GSYM(p_value, g_value);
    GSYM(xh, g_xh); GSYM(xl, g_xl); GSYM(zh, g_zallh); GSYM(zl, g_zalll);
    GSYM(qlh, g_qlath); GSYM(qll, g_qlatl);
    GSYM(qfh, g_qfh); GSYM(qfl, g_qfl); GSYM(kfh, g_kfh); GSYM(kfl, g_kfl);
    GSYM(vth, g_vth); GSYM(vtl, g_vtl); GSYM(hoh, g_hoh); GSYM(hol, g_hol);
    GSYM(pbh, g_pbh); GSYM(pbl, g_pbl);
    GSYM(WlatTh, g_WlatTh); GSYM(WlatTl, g_WlatTl);
    GSYM(WqdTh, g_WqdTh);   GSYM(WqdTl, g_WqdTl);
    GSYM(WquTh, g_WquTh);   GSYM(WquTl, g_WquTl);
    GSYM(WxrTh, g_WxrTh);   GSYM(WxrTl, g_WxrTl);
    GSYM(WkuTh, g_WkuTh);   GSYM(WkuTl, g_WkuTl);
    GSYM(WvuTh, g_WvuTh);   GSYM(WvuTl, g_WvuTl);
    GSYM(WkrTh, g_WkrTh);   GSYM(WkrTl, g_WkrTl);
    GSYM(WoTh, g_WoTh);     GSYM(WoTl, g_WoTl);

    const int SMB = 99328;   // 2 x 48KB stages + 1KB align pad
    cudaFuncSetAttribute(gemm_tc, cudaFuncAttributeMaxDynamicSharedMemorySize, SMB);
    dim3 tb(32, 8);

    // Launch order: our #4 is x@W_latent (ncu captures our 4th launch).
    split_kernel<<<4096, 256>>>(x, xh, xl, 4194304L);                                     // 1
    transpose_split<<<dim3(32, 64, 1), tb>>>(W_latent, WlatTh, WlatTl, 2048, 1024, 0, 0); // 2
    transpose_split<<<dim3(32, 64, 1), tb>>>(W_q_down, WqdTh,  WqdTl,  2048, 1024, 0, 0); // 3

    // 4: z_all[:,1024:,:] = x @ W_latent  (f32 out + split out)
    gemm_tc<<<dim3(16, 8, 2), 256, SMB>>>(
        xh, xl, WlatTh, WlatTl, out + OUT_ZALL + 1024L * 1024, nullptr,
        zh + 1024L * 1024, zl + 1024L * 1024,
        2048, 2048, 2048, 1024,
        1, 1024L * 2048, 0, 0, 0, 2048L * 1024, 0, 1.f);

    transpose_split<<<dim3(32, 32, 1), tb>>>(W_q_up, WquTh, WquTl, 1024, 1024, 0, 0);     // 5

    // 6: q_lat = x @ W_q_down + b (split output only)
    gemm_tc<<<dim3(16, 16, 1), 256, SMB>>>(
        xh, xl, WqdTh, WqdTl, nullptr, b_q_down, qlh, qll,
        2048, 2048, 2048, 1024, 1, 0, 0, 0, 0, 0, 0, 1.f);

    copy_concat_split<<<8192, 256>>>(z, out + OUT_ZALL, zh, zl);
    copy_concat_kernel<<<8192, 256>>>(key_rope, out + OUT_KRA);
    transpose_split<<<dim3(32, 32, 1), tb>>>(W_x_rope, WxrTh, WxrTl, 1024, 1024, 0, 0);
    transpose_split<<<dim3(32, 32, 1), tb>>>(W_k_up,   WkuTh, WkuTl, 1024, 1024, 0, 0);
    transpose_split<<<dim3(32, 32, 1), tb>>>(W_v_up,   WvuTh, WvuTl, 1024, 1024, 0, 0);
    transpose_split<<<dim3(32, 64, 1), tb>>>(W_k_rope, WkrTh, WkrTl, 2048, 1024, 0, 0);
    transpose_split<<<dim3(64, 32, 1), tb>>>(W_o,      WoTh,  WoTl,  1024, 2048, 0, 0);

    // query = q_lat @ W_q_up ; qx = q_lat @ W_x_rope
    gemm_tc<<<dim3(16, 16, 1), 256, SMB>>>(
        qlh, qll, WquTh, WquTl, p_query, nullptr, nullptr, nullptr,
        1024, 1024, 1024, 1024, 1, 0, 0, 0, 0, 0, 0, 1.f);
    gemm_tc<<<dim3(16, 16, 1), 256, SMB>>>(
        qlh, qll, WxrTh, WxrTl, p_qx, nullptr, nullptr, nullptr,
        1024, 1024, 1024, 1024, 1, 0, 0, 0, 0, 0, 0, 1.f);

    // key_c / value  (M=4096)
    gemm_tc<<<dim3(16, 32, 1), 256, SMB>>>(
        zh, zl, WkuTh, WkuTl, p_keyc, nullptr, nullptr, nullptr,
        1024, 1024, 1024, 1024, 1, 0, 0, 0, 0, 0, 0, 1.f);
    gemm_tc<<<dim3(16, 32, 1), 256, SMB>>>(
        zh, zl, WvuTh, WvuTl, p_value, nullptr, nullptr, nullptr,
        1024, 1024, 1024, 1024, 1, 0, 0, 0, 0, 0, 0, 1.f);

    // kx = x @ W_k_rope
    gemm_tc<<<dim3(16, 16, 1), 256, SMB>>>(
        xh, xl, WkrTh, WkrTl, p_kx, nullptr, nullptr, nullptr,
        2048, 2048, 2048, 1024, 1, 0, 0, 0, 0, 0, 0, 1.f);

    // rotary
    rotary_kernel<<<4096, 256>>>(p_qx, p_qrope, 0);
    rotary_kernel<<<4096, 256>>>(p_kx, out + OUT_KRA, 1);

    // pack+split q/k
    pack_q_split<<<16384, 256>>>(p_query, p_qrope, qfh, qfl);
    pack_k_split<<<32768, 256>>>(p_keyc, out + OUT_KRA, kfh, kfl);

    // value -> vt (transposed per batch)
    transpose_split<<<dim3(32, 64, 2), tb>>>(p_value, vth, vtl, 2048, 1024,
                                             2048L * 1024, 1024L * 2048);

    // scores = Q @ K^T / sqrt(128)
    gemm_tc<<<dim3(32, 8, 32), 256, SMB>>>(
        qfh, qfl, kfh, kfl, out + OUT_SCORES, nullptr, nullptr, nullptr,
        128, 128, 128, 2048,
        1, 1024L * 128, 0, 2048L * 128, 0, 1024L * 2048, 0,
        0.08838834764831845f);

    // dual softmax (single-exp)
    softmax_kernel<<<32768, 256>>>(out + OUT_SCORES, vlens, out + OUT_ATTN, pbh, pbl);

    // head_out = probs @ V  (split output)
    gemm_tc<<<dim3(1, 8, 32), 256, SMB>>>(
        pbh, pbl, vth, vtl, nullptr, nullptr, hoh, hol,
        2048, 2048, 2048, 1024,
        16, 16L * 1024 * 2048, 1024L * 2048,
        1024L * 2048, 64L * 2048,
        1024L * 1024, 64L,
        1.f);

    // out = head_out @ W_o
    gemm_tc<<<dim3(32, 16, 1), 256, SMB>>>(
        hoh, hol, WoTh, WoTl, out + OUT_OUT, nullptr, nullptr, nullptr,
        1024, 1024, 1024, 2048, 1, 0, 0, 0, 0, 0, 0, 1.f);
}